// round 7
// baseline (speedup 1.0000x reference)
#include <cuda_runtime.h>
#include <cstdint>
#include <cstddef>

// Problem dims
#define B_   256
#define IV   1000
#define D_   800
#define H1_  256
#define H2_  16
#define PH_  256

// Tiling
#define DK   16            // K-chunk staged in SMEM
#define IT   64            // intervals per CTA tile
#define GRID_I ((IV + IT - 1) / IT)   // 16

// Inter-kernel scratch: fc_input [B, IV]  (1 MB, static __device__ -> legal)
__device__ float g_fc[B_ * IV];

// Packed fp32x2 FMA (PTX-only on sm_103a; doubles fp32 throughput)
#define PACK2(out, lo, hi) \
    asm("mov.b64 %0, {%1, %2};" : "=l"(out) : "r"(lo), "r"(hi))
#define UNPACK2(lo, hi, in) \
    asm("mov.b64 {%0, %1}, %2;" : "=r"(lo), "=r"(hi) : "l"(in))
#define FMA2(d, a, b, c) \
    asm("fma.rn.f32x2 %0, %1, %2, %3;" : "=l"(d) : "l"(a), "l"(b), "l"(c))

// Dynamic SMEM layout (float offsets)
#define OFF_WS    0                    // [DK][256]   W1 chunk, d-major      (16 KB)
#define OFF_SS    4096                 // [DK][IT]    state chunk            (4 KB)   (reused as H2s[16][64])
#define OFF_W2S   5120                 // [16][256]   W2                     (16 KB)
#define OFF_B1S   9216                 // [256]
#define OFF_B2S   9472                 // [16]
#define OFF_W3S   9488                 // [16]
#define OFF_B3    9504                 // [1], pad to 9536
#define OFF_H1S   9536                 // [IT][260]   h1 tile, i-major, padded stride (conflict-free LDS.128)
#define H1S_STRIDE 260
#define SMEM_FLOATS (OFF_H1S + IT * H1S_STRIDE)     // 26176
#define SMEM_BYTES  (SMEM_FLOATS * 4)               // 104704 B -> 2 CTAs/SM

// ---------------------------------------------------------------------------
// Kernel 1: fused  relu(W1 @ S + b1) -> relu(W2 @ . + b2) -> W3 @ . + b3
// Grid: (GRID_I, B).  Block: 256 threads.
// Per CTA: C tile [256 h  x  64 i] for one batch, K=800 in DK=16 chunks.
// Thread tile: 16 h (as 8 f32x2 pairs) x 4 i  => 32 packed accumulators.
// ---------------------------------------------------------------------------
__global__ __launch_bounds__(256, 2)
void section_kernel(const float* __restrict__ state,
                    const float* __restrict__ W1, const float* __restrict__ b1,
                    const float* __restrict__ W2, const float* __restrict__ b2,
                    const float* __restrict__ W3, const float* __restrict__ b3)
{
    extern __shared__ float sm[];
    float* Ws  = sm + OFF_WS;     // Ws[d][h]
    float* Ss  = sm + OFF_SS;     // Ss[d][i]
    float* W2s = sm + OFF_W2S;    // W2s[g][h]
    float* b1s = sm + OFF_B1S;
    float* b2s = sm + OFF_B2S;
    float* w3s = sm + OFF_W3S;
    float* h1s = sm + OFF_H1S;    // h1s[i][h], stride 260

    const int tid = threadIdx.x;
    const int b   = blockIdx.y;
    const int i0  = blockIdx.x * IT;

    // ---- one-time staging of small tensors ----
    for (int idx = tid; idx < H2_ * H1_; idx += 256) W2s[idx] = W2[idx];
    if (tid < 256) b1s[tid] = b1[tid];
    if (tid < 16)  { b2s[tid] = b2[tid]; w3s[tid] = W3[tid]; }
    if (tid == 0)  sm[OFF_B3] = b3[0];

    const float* Sb = state + (size_t)b * (D_ * IV);

    // staging index precompute
    const int wh  = tid >> 2;         // h base lane for W loads (0..63, x4 iters)
    const int wdv = tid & 3;          // which 4-d group within chunk
    const int sdd = tid >> 4;         // d row for S loads (0..15)
    const int sii = (tid & 15) * 4;   // i offset (vec4)
    const int sgi = i0 + sii;
    const bool svalid = (sgi < IV);   // IV % 4 == 0 -> whole-vec4 validity

    float4 wreg[4];
    float4 sreg = make_float4(0.f, 0.f, 0.f, 0.f);

    // prologue: prefetch chunk 0 into registers
    {
        #pragma unroll
        for (int r = 0; r < 4; r++)
            wreg[r] = *(const float4*)(W1 + (r * 64 + wh) * D_ + wdv * 4);
        if (svalid)
            sreg = *(const float4*)(Sb + sdd * IV + sgi);
    }

    unsigned long long acc[8][4];
    #pragma unroll
    for (int hp = 0; hp < 8; hp++)
        #pragma unroll
        for (int ii = 0; ii < 4; ii++)
            acc[hp][ii] = 0ull;       // bits of (0.f, 0.f)

    const int hb = (tid >> 4) * 16;   // h base of this thread's 16-h strip
    const int ib = (tid & 15) * 4;    // i base of this thread's 4 intervals

    // ---- main K loop: stage(regs->smem) | prefetch next | compute ----
    for (int k0 = 0; k0 < D_; k0 += DK) {
        __syncthreads();              // prior compute done before overwrite
        #pragma unroll
        for (int r = 0; r < 4; r++) {
            const int h  = r * 64 + wh;
            const int db = wdv * 4;
            Ws[(db + 0) * H1_ + h] = wreg[r].x;
            Ws[(db + 1) * H1_ + h] = wreg[r].y;
            Ws[(db + 2) * H1_ + h] = wreg[r].z;
            Ws[(db + 3) * H1_ + h] = wreg[r].w;
        }
        *(float4*)(Ss + sdd * IT + sii) = sreg;
        __syncthreads();

        const int kn = k0 + DK;
        if (kn < D_) {                // prefetch next chunk (overlaps compute)
            #pragma unroll
            for (int r = 0; r < 4; r++)
                wreg[r] = *(const float4*)(W1 + (r * 64 + wh) * D_ + kn + wdv * 4);
            if (svalid)
                sreg = *(const float4*)(Sb + (kn + sdd) * IV + sgi);
        }

        #pragma unroll
        for (int dd = 0; dd < DK; dd++) {
            const float4 x = *(const float4*)(Ss + dd * IT + ib);
            unsigned long long xx0, xx1, xx2, xx3;
            { unsigned u = __float_as_uint(x.x); PACK2(xx0, u, u); }
            { unsigned u = __float_as_uint(x.y); PACK2(xx1, u, u); }
            { unsigned u = __float_as_uint(x.z); PACK2(xx2, u, u); }
            { unsigned u = __float_as_uint(x.w); PACK2(xx3, u, u); }
            const unsigned long long* wr =
                (const unsigned long long*)(Ws + dd * H1_ + hb);   // 8 h-pairs
            #pragma unroll
            for (int hp = 0; hp < 8; hp++) {
                const unsigned long long w = wr[hp];
                FMA2(acc[hp][0], w, xx0, acc[hp][0]);
                FMA2(acc[hp][1], w, xx1, acc[hp][1]);
                FMA2(acc[hp][2], w, xx2, acc[hp][2]);
                FMA2(acc[hp][3], w, xx3, acc[hp][3]);
            }
        }
    }

    // ---- epilogue: bias+relu -> h1s[i][h] ----
    #pragma unroll
    for (int hp = 0; hp < 8; hp++) {
        const int h0 = hb + hp * 2;
        const float bl = b1s[h0], bh = b1s[h0 + 1];
        #pragma unroll
        for (int ii = 0; ii < 4; ii++) {
            unsigned lo, hi;
            UNPACK2(lo, hi, acc[hp][ii]);
            float flo = fmaxf(__uint_as_float(lo) + bl, 0.f);
            float fhi = fmaxf(__uint_as_float(hi) + bh, 0.f);
            float* row = h1s + (ib + ii) * H1S_STRIDE;
            row[h0]     = flo;
            row[h0 + 1] = fhi;
        }
    }
    __syncthreads();   // all mainloop compute + h1 stores visible

    // ---- layer 2: H2[g][i] = relu(W2 @ h1 + b2), 256 threads = (4 g) x (64 i) ----
    {
        const int li = tid & 63;
        const int gq = tid >> 6;      // 0..3 -> g = gq*4 + j
        float a2[4] = { b2s[gq * 4 + 0], b2s[gq * 4 + 1],
                        b2s[gq * 4 + 2], b2s[gq * 4 + 3] };
        const float4* xr = (const float4*)(h1s + li * H1S_STRIDE);
        #pragma unroll 8
        for (int hv = 0; hv < H1_ / 4; hv++) {
            const float4 x = xr[hv];
            #pragma unroll
            for (int j = 0; j < 4; j++) {
                const float4 w = *(const float4*)(W2s + (gq * 4 + j) * H1_ + hv * 4);
                a2[j] += x.x * w.x + x.y * w.y + x.z * w.z + x.w * w.w;
            }
        }
        #pragma unroll
        for (int j = 0; j < 4; j++)
            Ss[(gq * 4 + j) * IT + li] = fmaxf(a2[j], 0.f);   // reuse Ss as H2s[16][64]
    }
    __syncthreads();

    // ---- layer 3: sec[i] = W3 @ H2 + b3 -> g_fc ----
    if (tid < IT) {
        float sec = sm[OFF_B3];
        #pragma unroll
        for (int g = 0; g < H2_; g++)
            sec += w3s[g] * Ss[g * IT + tid];
        const int gi = i0 + tid;
        if (gi < IV)
            g_fc[b * IV + gi] = sec;
    }
}

// ---------------------------------------------------------------------------
// Kernel 2: val[b] = Wv @ relu(Wp @ fc[b] + bp) + bv
// Grid: B blocks, 256 threads (one per PRED_H row), then block reduction.
// ---------------------------------------------------------------------------
__global__ __launch_bounds__(256)
void pred_kernel(const float* __restrict__ Wp, const float* __restrict__ bp,
                 const float* __restrict__ Wv, const float* __restrict__ bv,
                 float* __restrict__ out)
{
    __shared__ float fcb[IV];
    __shared__ float red[256];
    const int b   = blockIdx.x;
    const int tid = threadIdx.x;

    const float* f = g_fc + b * IV;
    for (int idx = tid; idx < IV; idx += 256) fcb[idx] = f[idx];
    __syncthreads();

    float acc = 0.f;
    const float4* wr = (const float4*)(Wp + tid * IV);
    #pragma unroll 5
    for (int kv = 0; kv < IV / 4; kv++) {
        const float4 w = wr[kv];
        const float4 x = *(const float4*)(fcb + kv * 4);
        acc += w.x * x.x + w.y * x.y + w.z * x.z + w.w * x.w;
    }
    const float y = fmaxf(acc + bp[tid], 0.f);
    red[tid] = y * Wv[tid];
    __syncthreads();
    for (int s = 128; s > 0; s >>= 1) {
        if (tid < s) red[tid] += red[tid + s];
        __syncthreads();
    }
    if (tid == 0) out[b] = red[0] + bv[0];
}

// ---------------------------------------------------------------------------
extern "C" void kernel_launch(void* const* d_in, const int* in_sizes, int n_in,
                              void* d_out, int out_size)
{
    const float* state = (const float*)d_in[0];
    const float* W1    = (const float*)d_in[1];
    const float* b1    = (const float*)d_in[2];
    const float* W2    = (const float*)d_in[3];
    const float* b2    = (const float*)d_in[4];
    const float* W3    = (const float*)d_in[5];
    const float* b3    = (const float*)d_in[6];
    const float* Wp    = (const float*)d_in[7];
    const float* bp    = (const float*)d_in[8];
    const float* Wv    = (const float*)d_in[9];
    const float* bv    = (const float*)d_in[10];
    float* out = (float*)d_out;

    // 104.7 KB dynamic SMEM (> 48 KB static limit) -> opt in every call
    // (idempotent, host-side, not a stream op: graph-capture safe)
    cudaFuncSetAttribute(section_kernel,
                         cudaFuncAttributeMaxDynamicSharedMemorySize, SMEM_BYTES);

    dim3 grid(GRID_I, B_);
    section_kernel<<<grid, 256, SMEM_BYTES>>>(state, W1, b1, W2, b2, W3, b3);
    pred_kernel<<<B_, 256>>>(Wp, bp, Wv, bv, out);
}

// round 9
// speedup vs baseline: 2.3915x; 2.3915x over previous
#include <cuda_runtime.h>
#include <cstdint>
#include <cstddef>

// ---------------- problem dims ----------------
#define B_   256
#define IV   1000
#define D_   800
#define H1_  256
#define H2_  16
#define PH_  256

// ---------------- section tiling ----------------
#define IT_M  128                 // intervals per CTA (N dim of GEMM)
#define NIT   8                   // 8*128 = 1024 >= 1000
#define KS    16                  // K per stage
#define NST   (D_ / KS)           // 50 stages
#define NRING 4                   // cp.async ring depth

// SMEM layout (bytes).  A slot: 256 rows x 20 floats (stride-20 pad) = 20480
//                        B slot: 16 rows x 136 floats (stride-136 pad) = 8704
#define ASLOT_BYTES 20480
#define BSLOT_BYTES 8704
#define SLOT_A_OFF(s) ((s) * ASLOT_BYTES)                  // 0 .. 81920
#define SLOT_B_OFF(s) (81920 + (s) * BSLOT_BYTES)          // .. 116736
// epilogue overlay (after mainloop): h1 [256 h][136 i] floats
#define EP_H1   0                   // 139264 bytes (overlaps pipeline slots)
#define EP_B1   139264              // 256 f
#define EP_B2   140288              // 16 f
#define EP_W3   140352              // 16 f
#define EP_B3   140416              // 1 f (pad 16)
#define EP_W2   140432              // W2t [256 h][16 g] = 16384 B
#define EP_H2   156816              // H2 [16 g][132 i] = 8448 B
#define SMEM_BYTES 165376

// ---------------- device scratch ----------------
__device__ __align__(16) float g_W1r[H1_ * D_];   // W1 rounded to tf32
__device__ __align__(16) float g_W2t[H1_ * H2_];  // W2 transposed [h][g]
__device__ __align__(16) float g_WpT[IV * PH_];   // Wp transposed [k][ph]
__device__ float g_fc[B_ * IV];

// ---------------- PTX helpers ----------------
__device__ __forceinline__ uint32_t smem_u32(const void* p) {
    uint32_t a;
    asm("{ .reg .u64 t; cvta.to.shared.u64 t, %1; cvt.u32.u64 %0, t; }"
        : "=r"(a) : "l"(p));
    return a;
}
__device__ __forceinline__ uint32_t f2tf32(float f) {
    uint32_t r; asm("cvt.rna.tf32.f32 %0, %1;" : "=r"(r) : "f"(f));
    return r;
}
#define PACK2(out, lo, hi) \
    asm("mov.b64 %0, {%1, %2};" : "=l"(out) : "r"(lo), "r"(hi))
#define UNPACK2(lo, hi, in) \
    asm("mov.b64 {%0, %1}, %2;" : "=r"(lo), "=r"(hi) : "l"(in))
#define FMA2(d, a, b, c) \
    asm("fma.rn.f32x2 %0, %1, %2, %3;" : "=l"(d) : "l"(a), "l"(b), "l"(c))

// cp.async 16B with zero-fill src-size (sm_80+, no arch-suffix gating)
#define CP_ASYNC16(dst_u32, src_ptr, vb) \
    asm volatile("cp.async.cg.shared.global [%0], [%1], 16, %2;" \
                 :: "r"(dst_u32), "l"(src_ptr), "r"(vb) : "memory")
#define CP_COMMIT() asm volatile("cp.async.commit_group;" ::: "memory")
#define CP_WAIT2()  asm volatile("cp.async.wait_group 2;" ::: "memory")

// tf32 warp MMA m16n8k8 (sm_80+ standard PTX, legacy HMMA path on sm_103)
__device__ __forceinline__ void mma_tf32(float c[4],
                                         uint32_t a0, uint32_t a1,
                                         uint32_t a2, uint32_t a3,
                                         uint32_t b0, uint32_t b1) {
    asm volatile(
        "mma.sync.aligned.m16n8k8.row.col.f32.tf32.tf32.f32 "
        "{%0,%1,%2,%3}, {%4,%5,%6,%7}, {%8,%9}, {%0,%1,%2,%3};"
        : "+f"(c[0]), "+f"(c[1]), "+f"(c[2]), "+f"(c[3])
        : "r"(a0), "r"(a1), "r"(a2), "r"(a3), "r"(b0), "r"(b1));
}

// ---------------------------------------------------------------------------
// prep kernels
// ---------------------------------------------------------------------------
__global__ void prep_w1(const float* __restrict__ W1) {
    int i = blockIdx.x * 256 + threadIdx.x;
    if (i < H1_ * D_) g_W1r[i] = __uint_as_float(f2tf32(W1[i]));
}
__global__ void prep_w2t(const float* __restrict__ W2) {
    int i = blockIdx.x * 256 + threadIdx.x;
    if (i < H2_ * H1_) {
        int g = i / H1_, h = i % H1_;
        g_W2t[h * H2_ + g] = W2[i];
    }
}
__global__ void prep_wpt(const float* __restrict__ Wp) {
    int i = blockIdx.x * 256 + threadIdx.x;
    if (i < PH_ * IV) {
        int ph = i / IV, k = i % IV;
        g_WpT[k * PH_ + ph] = Wp[i];
    }
}

// ---------------------------------------------------------------------------
// Kernel 1: fused section MLP. Grid (NIT, B_), 512 threads (16 warps).
// GEMM: D[h(256,M), i(128,N)] = W1[h,k] * state[k,i], K=800.
// Warp tile 64(M) x 32(N): warp grid 4(M) x 4(N). Acc 64 f32/thread.
// ---------------------------------------------------------------------------
__global__ __launch_bounds__(512, 1)
void section_kernel(const float* __restrict__ state,
                    const float* __restrict__ b1,
                    const float* __restrict__ b2,
                    const float* __restrict__ W3,
                    const float* __restrict__ b3)
{
    extern __shared__ char smc[];
    const uint32_t smem_base = smem_u32(smc);
    const int tid  = threadIdx.x;
    const int wid  = tid >> 5;
    const int lane = tid & 31;
    const int g4   = lane >> 2;       // groupID (0..7)
    const int tig  = lane & 3;        // threadID_in_group
    const int b    = blockIdx.y;
    const int i0   = blockIdx.x * IT_M;

    const int warp_h = (wid & 3) * 64;    // M offset of warp tile
    const int warp_i = (wid >> 2) * 32;   // N offset of warp tile

    // ---- stage epilogue constants (regions disjoint from pipeline slots) ----
    {
        float* eB1 = (float*)(smc + EP_B1);
        float* eW2 = (float*)(smc + EP_W2);
        if (tid < 256) eB1[tid] = b1[tid];
        for (int idx = tid; idx < H1_ * H2_; idx += 512) eW2[idx] = g_W2t[idx];
        if (tid < 16) {
            ((float*)(smc + EP_B2))[tid] = b2[tid];
            ((float*)(smc + EP_W3))[tid] = W3[tid];
        }
        if (tid == 0) *(float*)(smc + EP_B3) = b3[0];
    }

    // ---- cp.async staging thread mapping (fixed per thread) ----
    // A (W1r): 256 rows x 16 floats = 1024 x 16B ops -> 2 ops/thread
    const int ar0 = tid >> 2;             // rows ar0 and ar0+128
    const int akq = tid & 3;              // 16B quad within row
    // B (state): 16 rows x 128 floats = 512 x 16B ops -> 1 op/thread
    const int bk  = tid >> 5;             // k row 0..15
    const int biq = tid & 31;             // i quad
    const int bgi = i0 + biq * 4;
    const unsigned bvb = (bgi < IV) ? 16u : 0u;   // IV%4==0 -> all-or-nothing
    const size_t bcol = bvb ? (size_t)bgi : 0;    // clamp OOB src addr

    const float* Sb = state + (size_t)b * D_ * IV;

    auto issue_stage = [&](int s) {
        const int slot = s & (NRING - 1);
        const int k0 = s * KS;
        const uint32_t As = smem_base + SLOT_A_OFF(slot);
        const uint32_t Bs = smem_base + SLOT_B_OFF(slot);
        const float* a0p = g_W1r + (size_t)ar0 * D_ + k0 + akq * 4;
        CP_ASYNC16(As + ar0 * 80 + akq * 16, a0p, 16u);
        CP_ASYNC16(As + (ar0 + 128) * 80 + akq * 16, a0p + (size_t)128 * D_, 16u);
        CP_ASYNC16(Bs + bk * 544 + biq * 16, Sb + (size_t)(k0 + bk) * IV + bcol, bvb);
    };

    // prologue: fill 3 stages
    issue_stage(0); CP_COMMIT();
    issue_stage(1); CP_COMMIT();
    issue_stage(2); CP_COMMIT();

    float c[4][4][4];
    #pragma unroll
    for (int mf = 0; mf < 4; mf++)
        #pragma unroll
        for (int nf = 0; nf < 4; nf++)
            #pragma unroll
            for (int r = 0; r < 4; r++) c[mf][nf][r] = 0.f;

    // ---- mainloop ----
    #pragma unroll 1
    for (int s = 0; s < NST; s++) {
        CP_WAIT2();          // stage s complete (<=2 newer groups pending)
        __syncthreads();     // data visible; prior compute done before slot reuse

        if (s + 3 < NST) issue_stage(s + 3);
        CP_COMMIT();         // always commit (keeps wait_group accounting exact)

        const int slot = s & (NRING - 1);
        const float* Asf = (const float*)(smc + SLOT_A_OFF(slot));  // [256][20]
        const float* Bsf = (const float*)(smc + SLOT_B_OFF(slot));  // [16][136]

        #pragma unroll
        for (int k8 = 0; k8 < 2; k8++) {
            const int kb = k8 * 8;
            // A fragments (W1 pre-rounded to tf32): 4 M-frags
            uint32_t a[4][4];
            #pragma unroll
            for (int mf = 0; mf < 4; mf++) {
                const int r0 = warp_h + mf * 16 + g4;
                a[mf][0] = __float_as_uint(Asf[r0 * 20 + kb + tig]);
                a[mf][1] = __float_as_uint(Asf[(r0 + 8) * 20 + kb + tig]);
                a[mf][2] = __float_as_uint(Asf[r0 * 20 + kb + tig + 4]);
                a[mf][3] = __float_as_uint(Asf[(r0 + 8) * 20 + kb + tig + 4]);
            }
            // B fragments (state, rounded rna in-register): 4 N-frags
            uint32_t bf[4][2];
            #pragma unroll
            for (int nf = 0; nf < 4; nf++) {
                const int col = warp_i + nf * 8 + g4;
                bf[nf][0] = f2tf32(Bsf[(kb + tig) * 136 + col]);
                bf[nf][1] = f2tf32(Bsf[(kb + tig + 4) * 136 + col]);
            }
            #pragma unroll
            for (int mf = 0; mf < 4; mf++)
                #pragma unroll
                for (int nf = 0; nf < 4; nf++)
                    mma_tf32(c[mf][nf], a[mf][0], a[mf][1], a[mf][2], a[mf][3],
                             bf[nf][0], bf[nf][1]);
        }
    }
    __syncthreads();   // all compute done before h1 overlay overwrites slots

    // ---- epilogue: relu(D + b1) -> h1[h][i] in SMEM (stride 136) ----
    {
        const float* eB1 = (const float*)(smc + EP_B1);
        float* h1 = (float*)(smc + EP_H1);
        #pragma unroll
        for (int mf = 0; mf < 4; mf++) {
            #pragma unroll
            for (int half = 0; half < 2; half++) {
                const int h = warp_h + mf * 16 + g4 + half * 8;
                const float bv = eB1[h];
                #pragma unroll
                for (int nf = 0; nf < 4; nf++) {
                    const int i = warp_i + nf * 8 + 2 * tig;
                    h1[h * 136 + i]     = fmaxf(c[mf][nf][half * 2]     + bv, 0.f);
                    h1[h * 136 + i + 1] = fmaxf(c[mf][nf][half * 2 + 1] + bv, 0.f);
                }
            }
        }
    }
    __syncthreads();

    // ---- layer 2: H2[g][i] = relu(W2 @ h1 + b2); threads = 4 gq x 128 i ----
    {
        const int gq = tid >> 7;          // 0..3 (4 g each)
        const int il = tid & 127;
        const float* h1 = (const float*)(smc + EP_H1);
        const float* eW2 = (const float*)(smc + EP_W2);
        const float* eB2 = (const float*)(smc + EP_B2);
        float a2[4] = { eB2[gq * 4 + 0], eB2[gq * 4 + 1],
                        eB2[gq * 4 + 2], eB2[gq * 4 + 3] };
        #pragma unroll 8
        for (int h = 0; h < H1_; h++) {
            const float x = h1[h * 136 + il];              // coalesced, conflict-free
            const float4 w = *(const float4*)(eW2 + h * H2_ + gq * 4);  // broadcast
            a2[0] += x * w.x; a2[1] += x * w.y; a2[2] += x * w.z; a2[3] += x * w.w;
        }
        float* H2s = (float*)(smc + EP_H2);                // [16][132]
        #pragma unroll
        for (int j = 0; j < 4; j++)
            H2s[(gq * 4 + j) * 132 + il] = fmaxf(a2[j], 0.f);
    }
    __syncthreads();

    // ---- layer 3: sec[i] = W3 @ H2 + b3 -> g_fc ----
    if (tid < IT_M) {
        const float* H2s = (const float*)(smc + EP_H2);
        const float* eW3 = (const float*)(smc + EP_W3);
        float sec = *(const float*)(smc + EP_B3);
        #pragma unroll
        for (int g = 0; g < H2_; g++)
            sec += eW3[g] * H2s[g * 132 + tid];
        const int gi = i0 + tid;
        if (gi < IV) g_fc[b * IV + gi] = sec;
    }
}

// ---------------------------------------------------------------------------
// Kernel 2: predictor. Grid 64 blocks x 256 thr; 4 batches per block.
// ---------------------------------------------------------------------------
__global__ __launch_bounds__(256)
void pred_kernel(const float* __restrict__ bp,
                 const float* __restrict__ Wv, const float* __restrict__ bv,
                 float* __restrict__ out)
{
    __shared__ float fcsT[IV * 4 + 8];     // [k][4 batches]
    __shared__ float red[4][PH_];
    const int b0 = blockIdx.x * 4;
    const int tid = threadIdx.x;

    #pragma unroll
    for (int r = 0; r < 4; r++)
        for (int k = tid; k < IV; k += 256)
            fcsT[k * 4 + r] = g_fc[(b0 + r) * IV + k];
    __syncthreads();

    const int ph = tid;
    unsigned long long a01 = 0ull, a23 = 0ull;
    const float* wpt = g_WpT + ph;
    #pragma unroll 4
    for (int k = 0; k < IV; k++) {
        const uint32_t wu = __float_as_uint(wpt[(size_t)k * PH_]);   // coalesced
        unsigned long long ww; PACK2(ww, wu, wu);
        const unsigned long long p01 = *(const unsigned long long*)(fcsT + k * 4);
        const unsigned long long p23 = *(const unsigned long long*)(fcsT + k * 4 + 2);
        FMA2(a01, ww, p01, a01);
        FMA2(a23, ww, p23, a23);
    }
    uint32_t u0, u1, u2, u3;
    UNPACK2(u0, u1, a01);
    UNPACK2(u2, u3, a23);
    const float bpv = bp[ph], wvv = Wv[ph];
    red[0][ph] = fmaxf(__uint_as_float(u0) + bpv, 0.f) * wvv;
    red[1][ph] = fmaxf(__uint_as_float(u1) + bpv, 0.f) * wvv;
    red[2][ph] = fmaxf(__uint_as_float(u2) + bpv, 0.f) * wvv;
    red[3][ph] = fmaxf(__uint_as_float(u3) + bpv, 0.f) * wvv;
    __syncthreads();
    for (int s = 128; s > 0; s >>= 1) {
        if (tid < s) {
            #pragma unroll
            for (int r = 0; r < 4; r++) red[r][tid] += red[r][tid + s];
        }
        __syncthreads();
    }
    if (tid == 0) {
        const float bvv = bv[0];
        #pragma unroll
        for (int r = 0; r < 4; r++) out[b0 + r] = red[r][0] + bvv;
    }
}

// ---------------------------------------------------------------------------
extern "C" void kernel_launch(void* const* d_in, const int* in_sizes, int n_in,
                              void* d_out, int out_size)
{
    const float* state = (const float*)d_in[0];
    const float* W1    = (const float*)d_in[1];
    const float* b1    = (const float*)d_in[2];
    const float* W2    = (const float*)d_in[3];
    const float* b2    = (const float*)d_in[4];
    const float* W3    = (const float*)d_in[5];
    const float* b3    = (const float*)d_in[6];
    const float* Wp    = (const float*)d_in[7];
    const float* bp    = (const float*)d_in[8];
    const float* Wv    = (const float*)d_in[9];
    const float* bv    = (const float*)d_in[10];
    float* out = (float*)d_out;

    cudaFuncSetAttribute(section_kernel,
                         cudaFuncAttributeMaxDynamicSharedMemorySize, SMEM_BYTES);

    prep_w1 <<<(H1_ * D_ + 255) / 256, 256>>>(W1);
    prep_w2t<<<(H2_ * H1_ + 255) / 256, 256>>>(W2);
    prep_wpt<<<(PH_ * IV + 255) / 256, 256>>>(Wp);

    dim3 grid(NIT, B_);
    section_kernel<<<grid, 512, SMEM_BYTES>>>(state, b1, b2, W3, b3);
    pred_kernel<<<64, 256>>>(bp, Wv, bv, out);
}

// round 10
// speedup vs baseline: 2.6812x; 1.1211x over previous
#include <cuda_runtime.h>
#include <cstdint>
#include <cstddef>

// ---------------- problem dims ----------------
#define B_   256
#define IV   1000
#define D_   800
#define H1_  256
#define H2_  16
#define PH_  256

// ---------------- section tiling ----------------
#define IT_M  128                 // intervals per CTA (N dim of GEMM)
#define NIT   8                   // 8*128 = 1024 >= 1000
#define KS    32                  // K per stage
#define NST   (D_ / KS)           // 25 stages
// ring of 3 stages

// SMEM layout (bytes)
// A slot: 256 rows x 36 floats (stride-36 pad, ldmatrix conflict-free) = 36864
// B slot: 32 rows x 136 floats (stride-136 pad)                        = 17408
#define A_SL(s)  ((s) * 36864)              // 0 / 36864 / 73728
#define B_SL(s)  (110592 + (s) * 17408)     // 110592 / 128000 / 145408 ; end 162816
// post-mainloop overlay (written only after the final mainloop barrier)
#define EP_H1   0                 // h1 [256 h][136 i] f32 = 139264
#define EP_W2   139264            // W2t [256 h][16 g]     = 16384 -> 155648
#define EP_H2   155648            // H2 [16 g][132 i]      = 8448  -> 164096
// small consts staged at kernel start (in the gap ABOVE the ring: >= 162816)
#define EP_B1   164096            // 256 f -> 165120
#define EP_B2   165120            // 16 f  -> 165184
#define EP_W3   165184            // 16 f  -> 165248
#define EP_B3   165248            // 1 f   -> 165264
#define SMEM_BYTES 165376

// ---------------- device scratch ----------------
__device__ __align__(16) float g_W1r[H1_ * D_];   // W1 rounded to tf32
__device__ __align__(16) float g_W2t[H1_ * H2_];  // W2 transposed [h][g]
__device__ __align__(16) float g_WpT[IV * PH_];   // Wp transposed [k][ph]
__device__ float g_fc[B_ * IV];

// ---------------- PTX helpers ----------------
__device__ __forceinline__ uint32_t smem_u32(const void* p) {
    uint32_t a;
    asm("{ .reg .u64 t; cvta.to.shared.u64 t, %1; cvt.u32.u64 %0, t; }"
        : "=r"(a) : "l"(p));
    return a;
}
__device__ __forceinline__ uint32_t f2tf32(float f) {
    uint32_t r; asm("cvt.rna.tf32.f32 %0, %1;" : "=r"(r) : "f"(f));
    return r;
}
#define PACK2(out, lo, hi) \
    asm("mov.b64 %0, {%1, %2};" : "=l"(out) : "r"(lo), "r"(hi))
#define UNPACK2(lo, hi, in) \
    asm("mov.b64 {%0, %1}, %2;" : "=r"(lo), "=r"(hi) : "l"(in))
#define FMA2(d, a, b, c) \
    asm("fma.rn.f32x2 %0, %1, %2, %3;" : "=l"(d) : "l"(a), "l"(b), "l"(c))

// cp.async 16B with zero-fill src-size (sm_80+ standard PTX)
#define CP_ASYNC16(dst_u32, src_ptr, vb) \
    asm volatile("cp.async.cg.shared.global [%0], [%1], 16, %2;" \
                 :: "r"(dst_u32), "l"(src_ptr), "r"(vb) : "memory")
#define CP_COMMIT() asm volatile("cp.async.commit_group;" ::: "memory")
#define CP_WAIT1()  asm volatile("cp.async.wait_group 1;" ::: "memory")

// ldmatrix x4 (sm_75+ standard PTX)
#define LDSM_X4(r0, r1, r2, r3, addr) \
    asm volatile("ldmatrix.sync.aligned.m8n8.x4.shared.b16 {%0,%1,%2,%3}, [%4];" \
                 : "=r"(r0), "=r"(r1), "=r"(r2), "=r"(r3) : "r"(addr))

// tf32 warp MMA m16n8k8 (sm_80+ standard PTX, legacy HMMA path on sm_103)
__device__ __forceinline__ void mma_tf32(float c[4],
                                         uint32_t a0, uint32_t a1,
                                         uint32_t a2, uint32_t a3,
                                         uint32_t b0, uint32_t b1) {
    asm volatile(
        "mma.sync.aligned.m16n8k8.row.col.f32.tf32.tf32.f32 "
        "{%0,%1,%2,%3}, {%4,%5,%6,%7}, {%8,%9}, {%0,%1,%2,%3};"
        : "+f"(c[0]), "+f"(c[1]), "+f"(c[2]), "+f"(c[3])
        : "r"(a0), "r"(a1), "r"(a2), "r"(a3), "r"(b0), "r"(b1));
}

// ---------------------------------------------------------------------------
// prep kernels
// ---------------------------------------------------------------------------
__global__ void prep_w1(const float* __restrict__ W1) {
    int i = blockIdx.x * 256 + threadIdx.x;
    if (i < H1_ * D_) g_W1r[i] = __uint_as_float(f2tf32(W1[i]));
}
__global__ void prep_w2t(const float* __restrict__ W2) {
    int i = blockIdx.x * 256 + threadIdx.x;
    if (i < H2_ * H1_) {
        int g = i / H1_, h = i % H1_;
        g_W2t[h * H2_ + g] = W2[i];
    }
}
__global__ void prep_wpt(const float* __restrict__ Wp) {
    int i = blockIdx.x * 256 + threadIdx.x;
    if (i < PH_ * IV) {
        int ph = i / IV, k = i % IV;
        g_WpT[k * PH_ + ph] = Wp[i];
    }
}

// ---------------------------------------------------------------------------
// Kernel 1: fused section MLP. Grid (NIT, B_), 256 threads (8 warps).
// GEMM: D[h(256,M), i(128,N)] = W1[h,k] * state[k,i], K=800.
// Warp grid 4(M) x 2(N); warp tile 64h x 64i; 128 acc f32/thread.
// Fragment double-buffering + ldmatrix A + cp.async ring(3) of K=32 stages.
// ---------------------------------------------------------------------------
__global__ __launch_bounds__(256, 1)
void section_kernel(const float* __restrict__ state,
                    const float* __restrict__ b1,
                    const float* __restrict__ b2,
                    const float* __restrict__ W3,
                    const float* __restrict__ b3)
{
    extern __shared__ char smc[];
    const uint32_t smem_base = smem_u32(smc);
    const int tid  = threadIdx.x;
    const int wid  = tid >> 5;
    const int lane = tid & 31;
    const int g4   = lane >> 2;
    const int tig  = lane & 3;
    const int b    = blockIdx.y;
    const int i0   = blockIdx.x * IT_M;

    const int warp_h = (wid & 3) * 64;    // M offset of warp tile
    const int warp_i = (wid >> 2) * 64;   // N offset of warp tile

    // ---- stage small consts (region above the ring; safe from cp.async) ----
    {
        ((float*)(smc + EP_B1))[tid] = b1[tid];
        if (tid < 16) {
            ((float*)(smc + EP_B2))[tid] = b2[tid];
            ((float*)(smc + EP_W3))[tid] = W3[tid];
        }
        if (tid == 0) *(float*)(smc + EP_B3) = b3[0];
    }

    // ---- cp.async staging mapping ----
    const int aq = tid & 7;               // A: quad in row
    const int ar = tid >> 3;              // A: base row (0..31), rows ar+32j
    const int biq = tid & 31;             // B: quad (i)
    const int bgi = i0 + biq * 4;
    const unsigned bvb = (bgi < IV) ? 16u : 0u;   // IV%4==0 -> all-or-nothing
    const size_t bcol = bvb ? (size_t)bgi : 0;

    const float* Sb = state + (size_t)b * D_ * IV;

    auto issue_stage = [&](int k0, int slot) {
        const uint32_t As = smem_base + A_SL(slot);
        const uint32_t Bs = smem_base + B_SL(slot);
        #pragma unroll
        for (int j = 0; j < 8; j++) {
            const int row = ar + 32 * j;
            CP_ASYNC16(As + row * 144 + aq * 16,
                       g_W1r + (size_t)row * D_ + k0 + aq * 4, 16u);
        }
        #pragma unroll
        for (int j = 0; j < 4; j++) {
            const int k = (tid >> 5) + 8 * j;
            CP_ASYNC16(Bs + k * 544 + biq * 16,
                       Sb + (size_t)(k0 + k) * IV + bcol, bvb);
        }
    };

    // ldmatrix per-lane base offset (row = lane&15, col-quad = (lane>>4)*4)
    const uint32_t alane_off =
        (uint32_t)(((warp_h + (lane & 15)) * 36 + ((lane >> 4) * 4)) * 4);
    const int bcol0 = warp_i + g4;

    // prologue: fill 2 stages
    issue_stage(0, 0);       CP_COMMIT();
    issue_stage(KS, 1);      CP_COMMIT();

    float c[4][8][4];
    #pragma unroll
    for (int mf = 0; mf < 4; mf++)
        #pragma unroll
        for (int nf = 0; nf < 8; nf++)
            #pragma unroll
            for (int r = 0; r < 4; r++) c[mf][nf][r] = 0.f;

    uint32_t afr[2][4][4];
    uint32_t bfr[2][8][2];

#define LOAD_FRAGS(BUF, K8) do { \
    _Pragma("unroll") \
    for (int mf_ = 0; mf_ < 4; mf_++) \
        LDSM_X4(afr[BUF][mf_][0], afr[BUF][mf_][1], \
                afr[BUF][mf_][2], afr[BUF][mf_][3], \
                Aad + mf_ * 2304 + (K8) * 32); \
    _Pragma("unroll") \
    for (int nf_ = 0; nf_ < 8; nf_++) { \
        bfr[BUF][nf_][0] = f2tf32(Bsf[((K8) * 8 + tig) * 136 + bcol0 + nf_ * 8]); \
        bfr[BUF][nf_][1] = f2tf32(Bsf[((K8) * 8 + tig + 4) * 136 + bcol0 + nf_ * 8]); \
    } \
} while (0)

#define MMA_ALL(BUF) do { \
    _Pragma("unroll") \
    for (int mf_ = 0; mf_ < 4; mf_++) \
        _Pragma("unroll") \
        for (int nf_ = 0; nf_ < 8; nf_++) \
            mma_tf32(c[mf_][nf_], afr[BUF][mf_][0], afr[BUF][mf_][1], \
                     afr[BUF][mf_][2], afr[BUF][mf_][3], \
                     bfr[BUF][nf_][0], bfr[BUF][nf_][1]); \
} while (0)

    int slot = 0, slot_i = 2;
    #pragma unroll 1
    for (int s = 0; s < NST; s++) {
        CP_WAIT1();
        __syncthreads();                 // stage s visible; stage s-1 compute done

        if (s + 2 < NST) issue_stage((s + 2) * KS, slot_i);
        CP_COMMIT();                     // always commit (exact group accounting)

        const uint32_t Aad = smem_base + A_SL(slot) + alane_off;
        const float* Bsf = (const float*)(smc + B_SL(slot));

        // k8 software pipeline (loads of k8+1 overlap MMAs of k8)
        LOAD_FRAGS(0, 0);
        LOAD_FRAGS(1, 1);
        MMA_ALL(0);
        LOAD_FRAGS(0, 2);
        MMA_ALL(1);
        LOAD_FRAGS(1, 3);
        MMA_ALL(0);
        MMA_ALL(1);

        slot   = (slot   == 2) ? 0 : slot + 1;
        slot_i = (slot_i == 2) ? 0 : slot_i + 1;
    }
    __syncthreads();   // all MMAs done before h1 overlay overwrites the ring

    // ---- epilogue: relu(D + b1) -> h1[h][i] (stride 136), float2 stores ----
    {
        const float* eB1 = (const float*)(smc + EP_B1);
        float* h1 = (float*)(smc + EP_H1);
        #pragma unroll
        for (int mf = 0; mf < 4; mf++) {
            #pragma unroll
            for (int half = 0; half < 2; half++) {
                const int h = warp_h + mf * 16 + g4 + half * 8;
                const float bv = eB1[h];
                #pragma unroll
                for (int nf = 0; nf < 8; nf++) {
                    const int i = warp_i + nf * 8 + 2 * tig;
                    float2 v;
                    v.x = fmaxf(c[mf][nf][half * 2]     + bv, 0.f);
                    v.y = fmaxf(c[mf][nf][half * 2 + 1] + bv, 0.f);
                    *(float2*)(h1 + h * 136 + i) = v;
                }
            }
        }
        // stage W2t into its post-ring home (disjoint from h1)
        float* eW2 = (float*)(smc + EP_W2);
        for (int idx = tid; idx < H1_ * H2_; idx += 256) eW2[idx] = g_W2t[idx];
    }
    __syncthreads();

    // ---- layer 2: H2[g][i] = relu(W2 @ h1 + b2); 2 gq-halves x 128 i, f32x2 ----
    {
        const int gq = tid >> 7;          // 0..1 -> 8 g each (4 pairs)
        const int il = tid & 127;
        const float* h1 = (const float*)(smc + EP_H1);
        const float* eW2 = (const float*)(smc + EP_W2);
        const float* eB2 = (const float*)(smc + EP_B2);

        unsigned long long a2p[4];
        #pragma unroll
        for (int p = 0; p < 4; p++)
            a2p[p] = *(const unsigned long long*)(eB2 + gq * 8 + p * 2);

        #pragma unroll 8
        for (int h = 0; h < H1_; h++) {
            const uint32_t xu = __float_as_uint(h1[h * 136 + il]);
            unsigned long long xx; PACK2(xx, xu, xu);
            const unsigned long long* wp =
                (const unsigned long long*)(eW2 + h * H2_ + gq * 8);
            #pragma unroll
            for (int p = 0; p < 4; p++) FMA2(a2p[p], xx, wp[p], a2p[p]);
        }
        float* H2s = (float*)(smc + EP_H2);          // [16][132]
        #pragma unroll
        for (int p = 0; p < 4; p++) {
            uint32_t lo, hi;
            UNPACK2(lo, hi, a2p[p]);
            H2s[(gq * 8 + p * 2)     * 132 + il] = fmaxf(__uint_as_float(lo), 0.f);
            H2s[(gq * 8 + p * 2 + 1) * 132 + il] = fmaxf(__uint_as_float(hi), 0.f);
        }
    }
    __syncthreads();

    // ---- layer 3: sec[i] = W3 @ H2 + b3 -> g_fc ----
    if (tid < IT_M) {
        const float* H2s = (const float*)(smc + EP_H2);
        const float* eW3 = (const float*)(smc + EP_W3);
        float sec = *(const float*)(smc + EP_B3);
        #pragma unroll
        for (int g = 0; g < H2_; g++)
            sec += eW3[g] * H2s[g * 132 + tid];
        const int gi = i0 + tid;
        if (gi < IV) g_fc[b * IV + gi] = sec;
    }
}

// ---------------------------------------------------------------------------
// Kernel 2: predictor. Grid 64 blocks x 256 thr; 4 batches per block.
// ---------------------------------------------------------------------------
__global__ __launch_bounds__(256)
void pred_kernel(const float* __restrict__ bp,
                 const float* __restrict__ Wv, const float* __restrict__ bv,
                 float* __restrict__ out)
{
    __shared__ float fcsT[IV * 4 + 8];     // [k][4 batches]
    __shared__ float red[4][PH_];
    const int b0 = blockIdx.x * 4;
    const int tid = threadIdx.x;

    #pragma unroll
    for (int r = 0; r < 4; r++)
        for (int k = tid; k < IV; k += 256)
            fcsT[k * 4 + r] = g_fc[(b0 + r) * IV + k];
    __syncthreads();

    const int ph = tid;
    unsigned long long a01 = 0ull, a23 = 0ull;
    const float* wpt = g_WpT + ph;
    #pragma unroll 4
    for (int k = 0; k < IV; k++) {
        const uint32_t wu = __float_as_uint(wpt[(size_t)k * PH_]);   // coalesced
        unsigned long long ww; PACK2(ww, wu, wu);
        const unsigned long long p01 = *(const unsigned long long*)(fcsT + k * 4);
        const unsigned long long p23 = *(const unsigned long long*)(fcsT + k * 4 + 2);
        FMA2(a01, ww, p01, a01);
        FMA2(a23, ww, p23, a23);
    }
    uint32_t u0, u1, u2, u3;
    UNPACK2(u0, u1, a01);
    UNPACK2(u2, u3, a23);
    const float bpv = bp[ph], wvv = Wv[ph];
    red[0][ph] = fmaxf(__uint_as_float(u0) + bpv, 0.f) * wvv;
    red[1][ph] = fmaxf(__uint_as_float(u1) + bpv, 0.f) * wvv;
    red[2][ph] = fmaxf(__uint_as_float(u2) + bpv, 0.f) * wvv;
    red[3][ph] = fmaxf(__uint_as_float(u3) + bpv, 0.f) * wvv;
    __syncthreads();
    for (int s = 128; s > 0; s >>= 1) {
        if (tid < s) {
            #pragma unroll
            for (int r = 0; r < 4; r++) red[r][tid] += red[r][tid + s];
        }
        __syncthreads();
    }
    if (tid == 0) {
        const float bvv = bv[0];
        #pragma unroll
        for (int r = 0; r < 4; r++) out[b0 + r] = red[r][0] + bvv;
    }
}

// ---------------------------------------------------------------------------
extern "C" void kernel_launch(void* const* d_in, const int* in_sizes, int n_in,
                              void* d_out, int out_size)
{
    const float* state = (const float*)d_in[0];
    const float* W1    = (const float*)d_in[1];
    const float* b1    = (const float*)d_in[2];
    const float* W2    = (const float*)d_in[3];
    const float* b2    = (const float*)d_in[4];
    const float* W3    = (const float*)d_in[5];
    const float* b3    = (const float*)d_in[6];
    const float* Wp    = (const float*)d_in[7];
    const float* bp    = (const float*)d_in[8];
    const float* Wv    = (const float*)d_in[9];
    const float* bv    = (const float*)d_in[10];
    float* out = (float*)d_out;

    cudaFuncSetAttribute(section_kernel,
                         cudaFuncAttributeMaxDynamicSharedMemorySize, SMEM_BYTES);

    prep_w1 <<<(H1_ * D_ + 255) / 256, 256>>>(W1);
    prep_w2t<<<(H2_ * H1_ + 255) / 256, 256>>>(W2);
    prep_wpt<<<(PH_ * IV + 255) / 256, 256>>>(Wp);

    dim3 grid(NIT, B_);
    section_kernel<<<grid, 256, SMEM_BYTES>>>(state, b1, b2, W3, b3);
    pred_kernel<<<64, 256>>>(bp, Wv, bv, out);
}

// round 11
// speedup vs baseline: 2.6896x; 1.0032x over previous
#include <cuda_runtime.h>
#include <cstdint>
#include <cstddef>

// ---------------- problem dims ----------------
#define B_   256
#define IV   1000
#define D_   800
#define H1_  256
#define H2_  16
#define PH_  256

// ---------------- section tiling ----------------
#define IT_M  128                 // intervals per CTA (N dim of GEMM)
#define NIT   8                   // 8*128 = 1024 >= 1000
#define KS    32                  // K per stage
#define NST   (D_ / KS)           // 25 stages
// ring of 3 stages

// SMEM layout (bytes)
// A slot: 256 rows x 36 floats (stride-36 pad, ldmatrix conflict-free) = 36864
// B slot: 32 rows x 136 floats (stride-136 pad)                        = 17408
#define A_SL(s)  ((s) * 36864)              // 0 / 36864 / 73728
#define B_SL(s)  (110592 + (s) * 17408)     // 110592 / 128000 / 145408 ; end 162816
// post-mainloop overlay (written only after the final mainloop barrier)
#define EP_H1   0                 // h1 [256 h][136 i] f32 = 139264
#define EP_W2   139264            // W2t [256 h][16 g]     = 16384 -> 155648
#define EP_H2   155648            // H2 [16 g][132 i]      = 8448  -> 164096
// small consts staged at kernel start (in the gap ABOVE the ring: >= 162816)
#define EP_B1   164096            // 256 f -> 165120
#define EP_B2   165120            // 16 f  -> 165184
#define EP_W3   165184            // 16 f  -> 165248
#define EP_B3   165248            // 1 f   -> 165264
#define SMEM_BYTES 165376

// ---------------- device scratch ----------------
__device__ __align__(16) float g_W1r[H1_ * D_];   // W1 rounded to tf32
__device__ __align__(16) float g_W2t[H1_ * H2_];  // W2 transposed [h][g]
__device__ __align__(16) float g_WpT[IV * PH_];   // Wp transposed [k][ph]
__device__ float g_fc[B_ * IV];

// ---------------- PTX helpers ----------------
__device__ __forceinline__ uint32_t smem_u32(const void* p) {
    uint32_t a;
    asm("{ .reg .u64 t; cvta.to.shared.u64 t, %1; cvt.u32.u64 %0, t; }"
        : "=r"(a) : "l"(p));
    return a;
}
__device__ __forceinline__ uint32_t f2tf32(float f) {
    uint32_t r; asm("cvt.rna.tf32.f32 %0, %1;" : "=r"(r) : "f"(f));
    return r;
}
#define PACK2(out, lo, hi) \
    asm("mov.b64 %0, {%1, %2};" : "=l"(out) : "r"(lo), "r"(hi))
#define UNPACK2(lo, hi, in) \
    asm("mov.b64 {%0, %1}, %2;" : "=r"(lo), "=r"(hi) : "l"(in))
#define FMA2(d, a, b, c) \
    asm("fma.rn.f32x2 %0, %1, %2, %3;" : "=l"(d) : "l"(a), "l"(b), "l"(c))

// cp.async 16B with zero-fill src-size (sm_80+ standard PTX)
#define CP_ASYNC16(dst_u32, src_ptr, vb) \
    asm volatile("cp.async.cg.shared.global [%0], [%1], 16, %2;" \
                 :: "r"(dst_u32), "l"(src_ptr), "r"(vb) : "memory")
#define CP_COMMIT() asm volatile("cp.async.commit_group;" ::: "memory")
#define CP_WAIT1()  asm volatile("cp.async.wait_group 1;" ::: "memory")

// ldmatrix x4 (sm_75+ standard PTX)
#define LDSM_X4(r0, r1, r2, r3, addr) \
    asm volatile("ldmatrix.sync.aligned.m8n8.x4.shared.b16 {%0,%1,%2,%3}, [%4];" \
                 : "=r"(r0), "=r"(r1), "=r"(r2), "=r"(r3) : "r"(addr))

// tf32 warp MMA m16n8k8 (sm_80+ standard PTX, legacy HMMA path on sm_103)
__device__ __forceinline__ void mma_tf32(float c[4],
                                         uint32_t a0, uint32_t a1,
                                         uint32_t a2, uint32_t a3,
                                         uint32_t b0, uint32_t b1) {
    asm volatile(
        "mma.sync.aligned.m16n8k8.row.col.f32.tf32.tf32.f32 "
        "{%0,%1,%2,%3}, {%4,%5,%6,%7}, {%8,%9}, {%0,%1,%2,%3};"
        : "+f"(c[0]), "+f"(c[1]), "+f"(c[2]), "+f"(c[3])
        : "r"(a0), "r"(a1), "r"(a2), "r"(a3), "r"(b0), "r"(b1));
}

// ---------------------------------------------------------------------------
// prep kernels
// ---------------------------------------------------------------------------
__global__ void prep_w1(const float* __restrict__ W1) {
    int i = blockIdx.x * 256 + threadIdx.x;
    if (i < H1_ * D_) g_W1r[i] = __uint_as_float(f2tf32(W1[i]));
}
__global__ void prep_w2t(const float* __restrict__ W2) {
    int i = blockIdx.x * 256 + threadIdx.x;
    if (i < H2_ * H1_) {
        int g = i / H1_, h = i % H1_;
        g_W2t[h * H2_ + g] = W2[i];
    }
}
__global__ void prep_wpt(const float* __restrict__ Wp) {
    int i = blockIdx.x * 256 + threadIdx.x;
    if (i < PH_ * IV) {
        int ph = i / IV, k = i % IV;
        g_WpT[k * PH_ + ph] = Wp[i];
    }
}

// ---------------------------------------------------------------------------
// Kernel 1: fused section MLP. Grid (NIT, B_), 512 threads (16 warps).
// GEMM: D[h(256,M), i(128,N)] = W1[h,k] * state[k,i], K=800.
// Warp grid 4(M) x 4(N); warp tile 64h x 32i; 64 acc f32/thread.
// ldmatrix A + raw-f32 B (HMMA tf32 truncation) + cp.async ring(3), K=32 stages.
// ---------------------------------------------------------------------------
__global__ __launch_bounds__(512, 1)
void section_kernel(const float* __restrict__ state,
                    const float* __restrict__ b1,
                    const float* __restrict__ b2,
                    const float* __restrict__ W3,
                    const float* __restrict__ b3)
{
    extern __shared__ char smc[];
    const uint32_t smem_base = smem_u32(smc);
    const int tid  = threadIdx.x;
    const int wid  = tid >> 5;
    const int lane = tid & 31;
    const int g4   = lane >> 2;
    const int tig  = lane & 3;
    const int b    = blockIdx.y;
    const int i0   = blockIdx.x * IT_M;

    const int warp_h = (wid & 3) * 64;    // M offset of warp tile
    const int warp_i = (wid >> 2) * 32;   // N offset of warp tile

    // ---- stage small consts (region above the ring; safe from cp.async) ----
    {
        if (tid < 256) ((float*)(smc + EP_B1))[tid] = b1[tid];
        if (tid < 16) {
            ((float*)(smc + EP_B2))[tid] = b2[tid];
            ((float*)(smc + EP_W3))[tid] = W3[tid];
        }
        if (tid == 0) *(float*)(smc + EP_B3) = b3[0];
    }

    // ---- cp.async staging mapping (512 threads) ----
    const int aq  = tid & 7;              // A: quad in row
    const int ar  = tid >> 3;             // A: base row (0..63), rows ar+64j
    const int biq = tid & 31;             // B: i-quad
    const int bkb = tid >> 5;             // B: k base (0..15), rows bkb, bkb+16
    const int bgi = i0 + biq * 4;
    const unsigned bvb = (bgi < IV) ? 16u : 0u;   // IV%4==0 -> all-or-nothing
    const size_t bcol = bvb ? (size_t)bgi : 0;

    const float* Sb = state + (size_t)b * D_ * IV;

    auto issue_stage = [&](int k0, int slot) {
        const uint32_t As = smem_base + A_SL(slot);
        const uint32_t Bs = smem_base + B_SL(slot);
        #pragma unroll
        for (int j = 0; j < 4; j++) {
            const int row = ar + 64 * j;
            CP_ASYNC16(As + row * 144 + aq * 16,
                       g_W1r + (size_t)row * D_ + k0 + aq * 4, 16u);
        }
        #pragma unroll
        for (int j = 0; j < 2; j++) {
            const int k = bkb + 16 * j;
            CP_ASYNC16(Bs + k * 544 + biq * 16,
                       Sb + (size_t)(k0 + k) * IV + bcol, bvb);
        }
    };

    // ldmatrix per-lane base offset (row = lane&15, col-quad = (lane>>4)*4 floats)
    const uint32_t alane_off =
        (uint32_t)(((warp_h + (lane & 15)) * 36 + ((lane >> 4) * 4)) * 4);
    const int bcol0 = warp_i + g4;

    // prologue: fill 2 stages
    issue_stage(0, 0);       CP_COMMIT();
    issue_stage(KS, 1);      CP_COMMIT();

    float c[4][4][4];
    #pragma unroll
    for (int mf = 0; mf < 4; mf++)
        #pragma unroll
        for (int nf = 0; nf < 4; nf++)
            #pragma unroll
            for (int r = 0; r < 4; r++) c[mf][nf][r] = 0.f;

    int slot = 0, slot_i = 2;
    #pragma unroll 1
    for (int s = 0; s < NST; s++) {
        CP_WAIT1();
        __syncthreads();                 // stage s visible; stage s-1 compute done

        if (s + 2 < NST) issue_stage((s + 2) * KS, slot_i);
        CP_COMMIT();                     // always commit (exact group accounting)

        const uint32_t Aad = smem_base + A_SL(slot) + alane_off;
        const float* Bsf = (const float*)(smc + B_SL(slot));

        #pragma unroll
        for (int k8 = 0; k8 < 4; k8++) {
            uint32_t a[4][4];
            #pragma unroll
            for (int mf = 0; mf < 4; mf++)
                LDSM_X4(a[mf][0], a[mf][1], a[mf][2], a[mf][3],
                        Aad + mf * 2304 + k8 * 32);
            uint32_t bf[4][2];
            #pragma unroll
            for (int nf = 0; nf < 4; nf++) {
                // raw f32 bits: HMMA tf32 uses truncated mantissa (W1 is rna-rounded)
                bf[nf][0] = __float_as_uint(Bsf[(k8 * 8 + tig)     * 136 + bcol0 + nf * 8]);
                bf[nf][1] = __float_as_uint(Bsf[(k8 * 8 + tig + 4) * 136 + bcol0 + nf * 8]);
            }
            #pragma unroll
            for (int mf = 0; mf < 4; mf++)
                #pragma unroll
                for (int nf = 0; nf < 4; nf++)
                    mma_tf32(c[mf][nf], a[mf][0], a[mf][1], a[mf][2], a[mf][3],
                             bf[nf][0], bf[nf][1]);
        }

        slot   = (slot   == 2) ? 0 : slot + 1;
        slot_i = (slot_i == 2) ? 0 : slot_i + 1;
    }
    __syncthreads();   // all MMAs done before h1 overlay overwrites the ring

    // ---- epilogue: relu(D + b1) -> h1[h][i] (stride 136), float2 stores ----
    {
        const float* eB1 = (const float*)(smc + EP_B1);
        float* h1 = (float*)(smc + EP_H1);
        #pragma unroll
        for (int mf = 0; mf < 4; mf++) {
            #pragma unroll
            for (int half = 0; half < 2; half++) {
                const int h = warp_h + mf * 16 + g4 + half * 8;
                const float bv = eB1[h];
                #pragma unroll
                for (int nf = 0; nf < 4; nf++) {
                    const int i = warp_i + nf * 8 + 2 * tig;
                    float2 v;
                    v.x = fmaxf(c[mf][nf][half * 2]     + bv, 0.f);
                    v.y = fmaxf(c[mf][nf][half * 2 + 1] + bv, 0.f);
                    *(float2*)(h1 + h * 136 + i) = v;
                }
            }
        }
        // stage W2t into its post-ring home (disjoint from h1)
        float* eW2 = (float*)(smc + EP_W2);
        for (int idx = tid; idx < H1_ * H2_; idx += 512) eW2[idx] = g_W2t[idx];
    }
    __syncthreads();

    // ---- layer 2: H2[g][i] = relu(W2 @ h1 + b2); 4 gq x 128 i, f32x2 ----
    {
        const int gq = tid >> 7;          // 0..3 -> 4 g each (2 pairs)
        const int il = tid & 127;
        const float* h1 = (const float*)(smc + EP_H1);
        const float* eW2 = (const float*)(smc + EP_W2);
        const float* eB2 = (const float*)(smc + EP_B2);

        unsigned long long a2p[2];
        #pragma unroll
        for (int p = 0; p < 2; p++)
            a2p[p] = *(const unsigned long long*)(eB2 + gq * 4 + p * 2);

        #pragma unroll 8
        for (int h = 0; h < H1_; h++) {
            const uint32_t xu = __float_as_uint(h1[h * 136 + il]);
            unsigned long long xx; PACK2(xx, xu, xu);
            const unsigned long long* wp =
                (const unsigned long long*)(eW2 + h * H2_ + gq * 4);
            FMA2(a2p[0], xx, wp[0], a2p[0]);
            FMA2(a2p[1], xx, wp[1], a2p[1]);
        }
        float* H2s = (float*)(smc + EP_H2);          // [16][132]
        #pragma unroll
        for (int p = 0; p < 2; p++) {
            uint32_t lo, hi;
            UNPACK2(lo, hi, a2p[p]);
            H2s[(gq * 4 + p * 2)     * 132 + il] = fmaxf(__uint_as_float(lo), 0.f);
            H2s[(gq * 4 + p * 2 + 1) * 132 + il] = fmaxf(__uint_as_float(hi), 0.f);
        }
    }
    __syncthreads();

    // ---- layer 3: sec[i] = W3 @ H2 + b3 -> g_fc ----
    if (tid < IT_M) {
        const float* H2s = (const float*)(smc + EP_H2);
        const float* eW3 = (const float*)(smc + EP_W3);
        float sec = *(const float*)(smc + EP_B3);
        #pragma unroll
        for (int g = 0; g < H2_; g++)
            sec += eW3[g] * H2s[g * 132 + tid];
        const int gi = i0 + tid;
        if (gi < IV) g_fc[b * IV + gi] = sec;
    }
}

// ---------------------------------------------------------------------------
// Kernel 2: predictor. Grid 64 blocks x 256 thr; 4 batches per block.
// ---------------------------------------------------------------------------
__global__ __launch_bounds__(256)
void pred_kernel(const float* __restrict__ bp,
                 const float* __restrict__ Wv, const float* __restrict__ bv,
                 float* __restrict__ out)
{
    __shared__ float fcsT[IV * 4 + 8];     // [k][4 batches]
    __shared__ float red[4][PH_];
    const int b0 = blockIdx.x * 4;
    const int tid = threadIdx.x;

    #pragma unroll
    for (int r = 0; r < 4; r++)
        for (int k = tid; k < IV; k += 256)
            fcsT[k * 4 + r] = g_fc[(b0 + r) * IV + k];
    __syncthreads();

    const int ph = tid;
    unsigned long long a01 = 0ull, a23 = 0ull;
    const float* wpt = g_WpT + ph;
    #pragma unroll 4
    for (int k = 0; k < IV; k++) {
        const uint32_t wu = __float_as_uint(wpt[(size_t)k * PH_]);   // coalesced
        unsigned long long ww; PACK2(ww, wu, wu);
        const unsigned long long p01 = *(const unsigned long long*)(fcsT + k * 4);
        const unsigned long long p23 = *(const unsigned long long*)(fcsT + k * 4 + 2);
        FMA2(a01, ww, p01, a01);
        FMA2(a23, ww, p23, a23);
    }
    uint32_t u0, u1, u2, u3;
    UNPACK2(u0, u1, a01);
    UNPACK2(u2, u3, a23);
    const float bpv = bp[ph], wvv = Wv[ph];
    red[0][ph] = fmaxf(__uint_as_float(u0) + bpv, 0.f) * wvv;
    red[1][ph] = fmaxf(__uint_as_float(u1) + bpv, 0.f) * wvv;
    red[2][ph] = fmaxf(__uint_as_float(u2) + bpv, 0.f) * wvv;
    red[3][ph] = fmaxf(__uint_as_float(u3) + bpv, 0.f) * wvv;
    __syncthreads();
    for (int s = 128; s > 0; s >>= 1) {
        if (tid < s) {
            #pragma unroll
            for (int r = 0; r < 4; r++) red[r][tid] += red[r][tid + s];
        }
        __syncthreads();
    }
    if (tid == 0) {
        const float bvv = bv[0];
        #pragma unroll
        for (int r = 0; r < 4; r++) out[b0 + r] = red[r][0] + bvv;
    }
}

// ---------------------------------------------------------------------------
extern "C" void kernel_launch(void* const* d_in, const int* in_sizes, int n_in,
                              void* d_out, int out_size)
{
    const float* state = (const float*)d_in[0];
    const float* W1    = (const float*)d_in[1];
    const float* b1    = (const float*)d_in[2];
    const float* W2    = (const float*)d_in[3];
    const float* b2    = (const float*)d_in[4];
    const float* W3    = (const float*)d_in[5];
    const float* b3    = (const float*)d_in[6];
    const float* Wp    = (const float*)d_in[7];
    const float* bp    = (const float*)d_in[8];
    const float* Wv    = (const float*)d_in[9];
    const float* bv    = (const float*)d_in[10];
    float* out = (float*)d_out;

    cudaFuncSetAttribute(section_kernel,
                         cudaFuncAttributeMaxDynamicSharedMemorySize, SMEM_BYTES);

    prep_w1 <<<(H1_ * D_ + 255) / 256, 256>>>(W1);
    prep_w2t<<<(H2_ * H1_ + 255) / 256, 256>>>(W2);
    prep_wpt<<<(PH_ * IV + 255) / 256, 256>>>(Wp);

    dim3 grid(NIT, B_);
    section_kernel<<<grid, 512, SMEM_BYTES>>>(state, b1, b2, W3, b3);
    pred_kernel<<<64, 256>>>(bp, Wv, bv, out);
}

// round 13
// speedup vs baseline: 3.3798x; 1.2566x over previous
#include <cuda_runtime.h>
#include <cuda_fp16.h>
#include <cstdint>
#include <cstddef>

// ---------------- problem dims ----------------
#define B_   256
#define IV   1000
#define D_   800
#define H1_  256
#define H2_  16
#define PH_  256

// ---------------- section tiling ----------------
#define IT_M  128                 // intervals per CTA (N dim of GEMM)
#define NIT   8                   // 8*128 = 1024 >= 1000
#define KS    32                  // K per stage
#define NST   (D_ / KS)           // 25 stages
// ring of 3 stages

// SMEM layout (bytes)
// A slot: 256 rows x 80 B (64 B fp16 data + 16 B pad; 16B-aligned rows,
//         ldmatrix bank-clean: row*20 mod 32 all-distinct over 8 rows) = 20480
// B slot: 32 rows x 140 floats (560 B, 16B-aligned; 2-row k-stride bank-clean) = 17920
#define A_SL(s)  ((s) * 20480)              // 0 / 20480 / 40960 ; end 61440
#define B_SL(s)  (61440 + (s) * 17920)      // 61440 / 79360 / 97280 ; end 115200
// post-mainloop overlay (written only after the final mainloop barrier)
#define EP_H1   0                 // h1 [256 h][136 i] f32 = 139264
#define EP_W2   139264            // W2t [256 h][16 g]     = 16384 -> 155648
#define EP_H2   155648            // H2 [16 g][132 i]      = 8448  -> 164096
// small consts staged at kernel start (above ring AND overlay)
#define EP_B1   164096            // 256 f -> 165120
#define EP_B2   165120            // 16 f  -> 165184
#define EP_W3   165184            // 16 f  -> 165248
#define EP_B3   165248            // 1 f
#define SMEM_BYTES 165376

// ---------------- device scratch ----------------
__device__ __align__(16) __half g_W1h[H1_ * D_]; // W1 in fp16
__device__ __align__(16) float g_W2t[H1_ * H2_]; // W2 transposed [h][g]
__device__ __align__(16) float g_WpT[IV * PH_];  // Wp transposed [k][ph]
__device__ float g_fc[B_ * IV];

// ---------------- PTX helpers ----------------
__device__ __forceinline__ uint32_t smem_u32(const void* p) {
    uint32_t a;
    asm("{ .reg .u64 t; cvta.to.shared.u64 t, %1; cvt.u32.u64 %0, t; }"
        : "=r"(a) : "l"(p));
    return a;
}
#define PACK2(out, lo, hi) \
    asm("mov.b64 %0, {%1, %2};" : "=l"(out) : "r"(lo), "r"(hi))
#define UNPACK2(lo, hi, in) \
    asm("mov.b64 {%0, %1}, %2;" : "=r"(lo), "=r"(hi) : "l"(in))
#define FMA2(d, a, b, c) \
    asm("fma.rn.f32x2 %0, %1, %2, %3;" : "=l"(d) : "l"(a), "l"(b), "l"(c))

// pack two f32 -> f16x2 (second operand lands in the LOWER half)
__device__ __forceinline__ uint32_t cvt_f16x2(float lo, float hi) {
    uint32_t d;
    asm("cvt.rn.f16x2.f32 %0, %1, %2;" : "=r"(d) : "f"(hi), "f"(lo));
    return d;
}

// cp.async 16B with zero-fill src-size (sm_80+ standard PTX)
#define CP_ASYNC16(dst_u32, src_ptr, vb) \
    asm volatile("cp.async.cg.shared.global [%0], [%1], 16, %2;" \
                 :: "r"(dst_u32), "l"(src_ptr), "r"(vb) : "memory")
#define CP_COMMIT() asm volatile("cp.async.commit_group;" ::: "memory")
#define CP_WAIT1()  asm volatile("cp.async.wait_group 1;" ::: "memory")

// ldmatrix x4 (sm_75+ standard PTX) — native b16 on fp16 A
#define LDSM_X4(r0, r1, r2, r3, addr) \
    asm volatile("ldmatrix.sync.aligned.m8n8.x4.shared.b16 {%0,%1,%2,%3}, [%4];" \
                 : "=r"(r0), "=r"(r1), "=r"(r2), "=r"(r3) : "r"(addr))

// fp16 warp MMA m16n8k16 (sm_80+ standard PTX): 2x MACs/instr vs tf32 k8
__device__ __forceinline__ void mma_f16(float c[4],
                                        uint32_t a0, uint32_t a1,
                                        uint32_t a2, uint32_t a3,
                                        uint32_t b0, uint32_t b1) {
    asm volatile(
        "mma.sync.aligned.m16n8k16.row.col.f32.f16.f16.f32 "
        "{%0,%1,%2,%3}, {%4,%5,%6,%7}, {%8,%9}, {%0,%1,%2,%3};"
        : "+f"(c[0]), "+f"(c[1]), "+f"(c[2]), "+f"(c[3])
        : "r"(a0), "r"(a1), "r"(a2), "r"(a3), "r"(b0), "r"(b1));
}

// ---------------------------------------------------------------------------
// prep kernels
// ---------------------------------------------------------------------------
__global__ void prep_w1h(const float* __restrict__ W1) {
    int i = blockIdx.x * 256 + threadIdx.x;
    if (i < H1_ * D_) g_W1h[i] = __float2half_rn(W1[i]);
}
__global__ void prep_w2t(const float* __restrict__ W2) {
    int i = blockIdx.x * 256 + threadIdx.x;
    if (i < H2_ * H1_) {
        int g = i / H1_, h = i % H1_;
        g_W2t[h * H2_ + g] = W2[i];
    }
}
__global__ void prep_wpt(const float* __restrict__ Wp) {
    int i = blockIdx.x * 256 + threadIdx.x;
    if (i < PH_ * IV) {
        int ph = i / IV, k = i % IV;
        g_WpT[k * PH_ + ph] = Wp[i];
    }
}

// ---------------------------------------------------------------------------
// Kernel 1: fused section MLP. Grid (NIT, B_), 512 threads (16 warps).
// GEMM: D[h(256,M), i(128,N)] = W1[h,k] * state[k,i], K=800, fp16 inputs.
// Warp grid 4(M) x 4(N); warp tile 64h x 32i; 64 acc f32/thread.
// ldmatrix-b16 A + in-register f32->f16x2 B + cp.async ring(3), K=32 stages.
// ---------------------------------------------------------------------------
__global__ __launch_bounds__(512, 1)
void section_kernel(const float* __restrict__ state,
                    const float* __restrict__ b1,
                    const float* __restrict__ b2,
                    const float* __restrict__ W3,
                    const float* __restrict__ b3)
{
    extern __shared__ char smc[];
    const uint32_t smem_base = smem_u32(smc);
    const int tid  = threadIdx.x;
    const int wid  = tid >> 5;
    const int lane = tid & 31;
    const int g4   = lane >> 2;
    const int tig  = lane & 3;
    const int b    = blockIdx.y;
    const int i0   = blockIdx.x * IT_M;

    const int warp_h = (wid & 3) * 64;    // M offset of warp tile
    const int warp_i = (wid >> 2) * 32;   // N offset of warp tile

    // ---- stage small consts (above ring and overlay; never clobbered) ----
    {
        if (tid < 256) ((float*)(smc + EP_B1))[tid] = b1[tid];
        if (tid < 16) {
            ((float*)(smc + EP_B2))[tid] = b2[tid];
            ((float*)(smc + EP_W3))[tid] = W3[tid];
        }
        if (tid == 0) *(float*)(smc + EP_B3) = b3[0];
    }

    // ---- cp.async staging mapping (512 threads) ----
    // A (fp16): 256 rows x 64B data = 1024 x 16B ops -> 2 ops/thread
    const int aq  = tid & 3;              // A: 16B quad in row (4 quads = 64B)
    const int ar  = tid >> 2;             // A: base row (0..127), rows ar, ar+128
    // B (f32): 32 rows x 512B = 1024 x 16B ops -> 2 ops/thread
    const int biq = tid & 31;             // B: i-quad
    const int bkb = tid >> 5;             // B: k base (0..15), rows bkb, bkb+16
    const int bgi = i0 + biq * 4;
    const unsigned bvb = (bgi < IV) ? 16u : 0u;   // IV%4==0 -> all-or-nothing
    const size_t bcol = bvb ? (size_t)bgi : 0;

    const float* Sb = state + (size_t)b * D_ * IV;

    auto issue_stage = [&](int k0, int slot) {
        const uint32_t As = smem_base + A_SL(slot);
        const uint32_t Bs = smem_base + B_SL(slot);
        #pragma unroll
        for (int j = 0; j < 2; j++) {
            const int row = ar + 128 * j;
            CP_ASYNC16(As + row * 80 + aq * 16,
                       (const char*)g_W1h + (size_t)row * (D_ * 2) + k0 * 2 + aq * 16,
                       16u);
        }
        #pragma unroll
        for (int j = 0; j < 2; j++) {
            const int k = bkb + 16 * j;
            CP_ASYNC16(Bs + k * 560 + biq * 16,
                       Sb + (size_t)(k0 + k) * IV + bcol, bvb);
        }
    };

    // ldmatrix per-lane base: row = warp_h + (lane&15), col half = (lane>>4)*16B
    // (80-byte rows -> every address 16B-aligned)
    const uint32_t alane_off =
        (uint32_t)((warp_h + (lane & 15)) * 80 + ((lane >> 4) * 16));
    const int bcol0 = warp_i + g4;

    // prologue: fill 2 stages
    issue_stage(0, 0);       CP_COMMIT();
    issue_stage(KS, 1);      CP_COMMIT();

    float c[4][4][4];
    #pragma unroll
    for (int mf = 0; mf < 4; mf++)
        #pragma unroll
        for (int nf = 0; nf < 4; nf++)
            #pragma unroll
            for (int r = 0; r < 4; r++) c[mf][nf][r] = 0.f;

    int slot = 0, slot_i = 2;
    #pragma unroll 1
    for (int s = 0; s < NST; s++) {
        CP_WAIT1();
        __syncthreads();                 // stage s visible; stage s-1 compute done

        if (s + 2 < NST) issue_stage((s + 2) * KS, slot_i);
        CP_COMMIT();                     // always commit (exact group accounting)

        const uint32_t Aad = smem_base + A_SL(slot) + alane_off;
        const float* Bsf = (const float*)(smc + B_SL(slot));

        #pragma unroll
        for (int k16 = 0; k16 < 2; k16++) {
            uint32_t a[4][4];
            #pragma unroll
            for (int mf = 0; mf < 4; mf++)
                LDSM_X4(a[mf][0], a[mf][1], a[mf][2], a[mf][3],
                        Aad + mf * 1280 + k16 * 32);
            // B frags: b0 holds k=2tig,2tig+1 (lo,hi); b1 holds k+8,k+9
            uint32_t bf[4][2];
            #pragma unroll
            for (int nf = 0; nf < 4; nf++) {
                const float* bp = Bsf + (k16 * 16 + 2 * tig) * 140 + bcol0 + nf * 8;
                bf[nf][0] = cvt_f16x2(bp[0],       bp[140]);
                bf[nf][1] = cvt_f16x2(bp[8 * 140], bp[9 * 140]);
            }
            #pragma unroll
            for (int mf = 0; mf < 4; mf++)
                #pragma unroll
                for (int nf = 0; nf < 4; nf++)
                    mma_f16(c[mf][nf], a[mf][0], a[mf][1], a[mf][2], a[mf][3],
                            bf[nf][0], bf[nf][1]);
        }

        slot   = (slot   == 2) ? 0 : slot + 1;
        slot_i = (slot_i == 2) ? 0 : slot_i + 1;
    }
    __syncthreads();   // all MMAs done before h1 overlay overwrites the ring

    // ---- epilogue: relu(D + b1) -> h1[h][i] (stride 136), float2 stores ----
    {
        const float* eB1 = (const float*)(smc + EP_B1);
        float* h1 = (float*)(smc + EP_H1);
        #pragma unroll
        for (int mf = 0; mf < 4; mf++) {
            #pragma unroll
            for (int half = 0; half < 2; half++) {
                const int h = warp_h + mf * 16 + g4 + half * 8;
                const float bv = eB1[h];
                #pragma unroll
                for (int nf = 0; nf < 4; nf++) {
                    const int i = warp_i + nf * 8 + 2 * tig;
                    float2 v;
                    v.x = fmaxf(c[mf][nf][half * 2]     + bv, 0.f);
                    v.y = fmaxf(c[mf][nf][half * 2 + 1] + bv, 0.f);
                    *(float2*)(h1 + h * 136 + i) = v;
                }
            }
        }
        // stage W2t into its post-ring home (disjoint from h1)
        float* eW2 = (float*)(smc + EP_W2);
        for (int idx = tid; idx < H1_ * H2_; idx += 512) eW2[idx] = g_W2t[idx];
    }
    __syncthreads();

    // ---- layer 2: H2[g][i] = relu(W2 @ h1 + b2); 4 gq x 128 i, f32x2 ----
    {
        const int gq = tid >> 7;          // 0..3 -> 4 g each (2 pairs)
        const int il = tid & 127;
        const float* h1 = (const float*)(smc + EP_H1);
        const float* eW2 = (const float*)(smc + EP_W2);
        const float* eB2 = (const float*)(smc + EP_B2);

        unsigned long long a2p[2];
        #pragma unroll
        for (int p = 0; p < 2; p++)
            a2p[p] = *(const unsigned long long*)(eB2 + gq * 4 + p * 2);

        #pragma unroll 8
        for (int h = 0; h < H1_; h++) {
            const uint32_t xu = __float_as_uint(h1[h * 136 + il]);
            unsigned long long xx; PACK2(xx, xu, xu);
            const unsigned long long* wp =
                (const unsigned long long*)(eW2 + h * H2_ + gq * 4);
            FMA2(a2p[0], xx, wp[0], a2p[0]);
            FMA2(a2p[1], xx, wp[1], a2p[1]);
        }
        float* H2s = (float*)(smc + EP_H2);          // [16][132]
        #pragma unroll
        for (int p = 0; p < 2; p++) {
            uint32_t lo, hi;
            UNPACK2(lo, hi, a2p[p]);
            H2s[(gq * 4 + p * 2)     * 132 + il] = fmaxf(__uint_as_float(lo), 0.f);
            H2s[(gq * 4 + p * 2 + 1) * 132 + il] = fmaxf(__uint_as_float(hi), 0.f);
        }
    }
    __syncthreads();

    // ---- layer 3: sec[i] = W3 @ H2 + b3 -> g_fc ----
    if (tid < IT_M) {
        const float* H2s = (const float*)(smc + EP_H2);
        const float* eW3 = (const float*)(smc + EP_W3);
        float sec = *(const float*)(smc + EP_B3);
        #pragma unroll
        for (int g = 0; g < H2_; g++)
            sec += eW3[g] * H2s[g * 132 + tid];
        const int gi = i0 + tid;
        if (gi < IV) g_fc[b * IV + gi] = sec;
    }
}

// ---------------------------------------------------------------------------
// Kernel 2: predictor. Grid 64 blocks x 256 thr; 4 batches per block.
// ---------------------------------------------------------------------------
__global__ __launch_bounds__(256)
void pred_kernel(const float* __restrict__ bp,
                 const float* __restrict__ Wv, const float* __restrict__ bv,
                 float* __restrict__ out)
{
    __shared__ float fcsT[IV * 4 + 8];     // [k][4 batches]
    __shared__ float red[4][PH_];
    const int b0 = blockIdx.x * 4;
    const int tid = threadIdx.x;

    #pragma unroll
    for (int r = 0; r < 4; r++)
        for (int k = tid; k < IV; k += 256)
            fcsT[k * 4 + r] = g_fc[(b0 + r) * IV + k];
    __syncthreads();

    const int ph = tid;
    unsigned long long a01 = 0ull, a23 = 0ull;
    const float* wpt = g_WpT + ph;
    #pragma unroll 4
    for (int k = 0; k < IV; k++) {
        const uint32_t wu = __float_as_uint(wpt[(size_t)k * PH_]);   // coalesced
        unsigned long long ww; PACK2(ww, wu, wu);
        const unsigned long long p01 = *(const unsigned long long*)(fcsT + k * 4);
        const unsigned long long p23 = *(const unsigned long long*)(fcsT + k * 4 + 2);
        FMA2(a01, ww, p01, a01);
        FMA2(a23, ww, p23, a23);
    }
    uint32_t u0, u1, u2, u3;
    UNPACK2(u0, u1, a01);
    UNPACK2(u2, u3, a23);
    const float bpv = bp[ph], wvv = Wv[ph];
    red[0][ph] = fmaxf(__uint_as_float(u0) + bpv, 0.f) * wvv;
    red[1][ph] = fmaxf(__uint_as_float(u1) + bpv, 0.f) * wvv;
    red[2][ph] = fmaxf(__uint_as_float(u2) + bpv, 0.f) * wvv;
    red[3][ph] = fmaxf(__uint_as_float(u3) + bpv, 0.f) * wvv;
    __syncthreads();
    for (int s = 128; s > 0; s >>= 1) {
        if (tid < s) {
            #pragma unroll
            for (int r = 0; r < 4; r++) red[r][tid] += red[r][tid + s];
        }
        __syncthreads();
    }
    if (tid == 0) {
        const float bvv = bv[0];
        #pragma unroll
        for (int r = 0; r < 4; r++) out[b0 + r] = red[r][0] + bvv;
    }
}

// ---------------------------------------------------------------------------
extern "C" void kernel_launch(void* const* d_in, const int* in_sizes, int n_in,
                              void* d_out, int out_size)
{
    const float* state = (const float*)d_in[0];
    const float* W1    = (const float*)d_in[1];
    const float* b1    = (const float*)d_in[2];
    const float* W2    = (const float*)d_in[3];
    const float* b2    = (const float*)d_in[4];
    const float* W3    = (const float*)d_in[5];
    const float* b3    = (const float*)d_in[6];
    const float* Wp    = (const float*)d_in[7];
    const float* bp    = (const float*)d_in[8];
    const float* Wv    = (const float*)d_in[9];
    const float* bv    = (const float*)d_in[10];
    float* out = (float*)d_out;

    cudaFuncSetAttribute(section_kernel,
                         cudaFuncAttributeMaxDynamicSharedMemorySize, SMEM_BYTES);

    prep_w1h<<<(H1_ * D_ + 255) / 256, 256>>>(W1);
    prep_w2t<<<(H2_ * H1_ + 255) / 256, 256>>>(W2);
    prep_wpt<<<(PH_ * IV + 255) / 256, 256>>>(Wp);

    dim3 grid(NIT, B_);
    section_kernel<<<grid, 512, SMEM_BYTES>>>(state, b1, b2, W3, b3);
    pred_kernel<<<64, 256>>>(bp, Wv, bv, out);
}

// round 14
// speedup vs baseline: 3.6400x; 1.0770x over previous
#include <cuda_runtime.h>
#include <cuda_fp16.h>
#include <cstdint>
#include <cstddef>

// ---------------- problem dims ----------------
#define B_   256
#define IV   1000
#define D_   800
#define H1_  256
#define H2_  16
#define PH_  256

// ---------------- section tiling ----------------
#define IT_M  128                 // intervals per CTA (N dim of GEMM)
#define NIT   8                   // 8*128 = 1024 >= 1000
#define KS    80                  // K per stage
#define NST   (D_ / KS)           // 10 stages
// double-buffer ring (2 slots)

// SMEM layout (bytes)
// A slot: 256 rows x 176 B (160 B fp16 data + 16 B pad). 16B-aligned rows;
//         ldmatrix bank-clean: 16B-group idx = 11*row mod 32, distinct over 8 rows.
// B slot: 80 rows x 560 B (140 floats; 2-row k-stride bank-clean as in R13).
#define ASLOT  45056                         // 256*176
#define BSLOT  44800                         // 80*560
#define SLOT   (ASLOT + BSLOT)               // 89856
#define A_SL(s)  ((s) * SLOT)                // 0 / 89856
#define B_SL(s)  ((s) * SLOT + ASLOT)        // 45056 / 134912 ; ring ends 179712
// post-mainloop overlay (written only after the final mainloop barrier)
#define EP_H1   0                 // h1 [256 h][136 i] f32 = 139264
#define EP_W2   139264            // W2t [256 h][16 g]     = 16384 -> 155648
#define EP_H2   155648            // H2 [16 g][132 i]      = 8448  -> 164096
// small consts staged at kernel start (ABOVE the ring: >= 179712)
#define EP_B1   179712            // 256 f -> 180736
#define EP_B2   180736            // 16 f  -> 180800
#define EP_W3   180800            // 16 f  -> 180864
#define EP_B3   180864            // 1 f
#define SMEM_BYTES 180992

// ---------------- device scratch ----------------
__device__ __align__(16) __half g_W1h[H1_ * D_]; // W1 in fp16
__device__ __align__(16) float g_W2t[H1_ * H2_]; // W2 transposed [h][g]
__device__ __align__(16) float g_WpT[IV * PH_];  // Wp transposed [k][ph]
__device__ float g_fc[B_ * IV];

// ---------------- PTX helpers ----------------
__device__ __forceinline__ uint32_t smem_u32(const void* p) {
    uint32_t a;
    asm("{ .reg .u64 t; cvta.to.shared.u64 t, %1; cvt.u32.u64 %0, t; }"
        : "=r"(a) : "l"(p));
    return a;
}
#define PACK2(out, lo, hi) \
    asm("mov.b64 %0, {%1, %2};" : "=l"(out) : "r"(lo), "r"(hi))
#define UNPACK2(lo, hi, in) \
    asm("mov.b64 {%0, %1}, %2;" : "=r"(lo), "=r"(hi) : "l"(in))
#define FMA2(d, a, b, c) \
    asm("fma.rn.f32x2 %0, %1, %2, %3;" : "=l"(d) : "l"(a), "l"(b), "l"(c))

// pack two f32 -> f16x2 (second PTX operand lands in the LOWER half)
__device__ __forceinline__ uint32_t cvt_f16x2(float lo, float hi) {
    uint32_t d;
    asm("cvt.rn.f16x2.f32 %0, %1, %2;" : "=r"(d) : "f"(hi), "f"(lo));
    return d;
}

// cp.async 16B with zero-fill src-size (sm_80+ standard PTX)
#define CP_ASYNC16(dst_u32, src_ptr, vb) \
    asm volatile("cp.async.cg.shared.global [%0], [%1], 16, %2;" \
                 :: "r"(dst_u32), "l"(src_ptr), "r"(vb) : "memory")
#define CP_COMMIT() asm volatile("cp.async.commit_group;" ::: "memory")
#define CP_WAIT0()  asm volatile("cp.async.wait_group 0;" ::: "memory")

// ldmatrix x4 (sm_75+ standard PTX) — native b16 on fp16 A
#define LDSM_X4(r0, r1, r2, r3, addr) \
    asm volatile("ldmatrix.sync.aligned.m8n8.x4.shared.b16 {%0,%1,%2,%3}, [%4];" \
                 : "=r"(r0), "=r"(r1), "=r"(r2), "=r"(r3) : "r"(addr))

// fp16 warp MMA m16n8k16 (sm_80+ standard PTX)
__device__ __forceinline__ void mma_f16(float c[4],
                                        uint32_t a0, uint32_t a1,
                                        uint32_t a2, uint32_t a3,
                                        uint32_t b0, uint32_t b1) {
    asm volatile(
        "mma.sync.aligned.m16n8k16.row.col.f32.f16.f16.f32 "
        "{%0,%1,%2,%3}, {%4,%5,%6,%7}, {%8,%9}, {%0,%1,%2,%3};"
        : "+f"(c[0]), "+f"(c[1]), "+f"(c[2]), "+f"(c[3])
        : "r"(a0), "r"(a1), "r"(a2), "r"(a3), "r"(b0), "r"(b1));
}

// ---------------------------------------------------------------------------
// merged prep kernel: W1->fp16, W2 transpose, Wp transpose
// ---------------------------------------------------------------------------
__global__ void prep_all(const float* __restrict__ W1,
                         const float* __restrict__ W2,
                         const float* __restrict__ Wp)
{
    const int i = blockIdx.x * 256 + threadIdx.x;
    if (i < H1_ * D_) g_W1h[i] = __float2half_rn(W1[i]);
    if (i < H2_ * H1_) {
        const int g = i / H1_, h = i % H1_;
        g_W2t[h * H2_ + g] = W2[i];
    }
    if (i < PH_ * IV) {
        const int ph = i / IV, k = i % IV;
        g_WpT[k * PH_ + ph] = Wp[i];
    }
}

// ---------------------------------------------------------------------------
// Kernel 1: fused section MLP. Grid (NIT, B_), 512 threads (16 warps).
// GEMM: D[h(256,M), i(128,N)] = W1[h,k] * state[k,i], K=800, fp16 inputs.
// Warp grid 4(M) x 4(N); warp tile 64h x 32i; 64 acc f32/thread.
// KS=80 stages (10 total), double-buffered; 5 unrolled k16 per stage
// with no internal barriers -> ptxas software-pipelines frag loads.
// ---------------------------------------------------------------------------
__global__ __launch_bounds__(512, 1)
void section_kernel(const float* __restrict__ state,
                    const float* __restrict__ b1,
                    const float* __restrict__ b2,
                    const float* __restrict__ W3,
                    const float* __restrict__ b3)
{
    extern __shared__ char smc[];
    const uint32_t smem_base = smem_u32(smc);
    const int tid  = threadIdx.x;
    const int wid  = tid >> 5;
    const int lane = tid & 31;
    const int g4   = lane >> 2;
    const int tig  = lane & 3;
    const int b    = blockIdx.y;
    const int i0   = blockIdx.x * IT_M;

    const int warp_h = (wid & 3) * 64;    // M offset of warp tile
    const int warp_i = (wid >> 2) * 32;   // N offset of warp tile

    // ---- stage small consts (above the ring; never clobbered) ----
    {
        if (tid < 256) ((float*)(smc + EP_B1))[tid] = b1[tid];
        if (tid < 16) {
            ((float*)(smc + EP_B2))[tid] = b2[tid];
            ((float*)(smc + EP_W3))[tid] = W3[tid];
        }
        if (tid == 0) *(float*)(smc + EP_B3) = b3[0];
    }

    // ---- cp.async staging mapping (512 threads) ----
    // A: 256 rows x 160B = 2560 x 16B ops -> 5/thread (rows via /10, precomputed)
    int arow[5], aqd[5];
    #pragma unroll
    for (int j = 0; j < 5; j++) {
        const int o = tid + 512 * j;
        arow[j] = o / 10;
        aqd[j]  = o % 10;
    }
    // B: 80 rows x 512B = 2560 x 16B ops -> 5/thread (32 divides 512: clean)
    const int biq = tid & 31;             // i-quad
    const int bkb = tid >> 5;             // k base (0..15), rows bkb + 16j
    const int bgi = i0 + biq * 4;
    const unsigned bvb = (bgi < IV) ? 16u : 0u;   // IV%4==0 -> all-or-nothing
    const size_t bcol = bvb ? (size_t)bgi : 0;

    const float* Sb = state + (size_t)b * D_ * IV;

    auto issue_stage = [&](int k0, int slot) {
        const uint32_t As = smem_base + A_SL(slot);
        const uint32_t Bs = smem_base + B_SL(slot);
        #pragma unroll
        for (int j = 0; j < 5; j++) {
            CP_ASYNC16(As + arow[j] * 176 + aqd[j] * 16,
                       (const char*)g_W1h + (size_t)arow[j] * (D_ * 2)
                                          + k0 * 2 + aqd[j] * 16, 16u);
        }
        #pragma unroll
        for (int j = 0; j < 5; j++) {
            const int k = bkb + 16 * j;
            CP_ASYNC16(Bs + k * 560 + biq * 16,
                       Sb + (size_t)(k0 + k) * IV + bcol, bvb);
        }
    };

    // ldmatrix per-lane base: row = warp_h + (lane&15), col half = (lane>>4)*16B
    const uint32_t alane_off =
        (uint32_t)((warp_h + (lane & 15)) * 176 + ((lane >> 4) * 16));
    const int bcol0 = warp_i + g4;

    // prologue: fill slot 0
    issue_stage(0, 0);       CP_COMMIT();

    float c[4][4][4];
    #pragma unroll
    for (int mf = 0; mf < 4; mf++)
        #pragma unroll
        for (int nf = 0; nf < 4; nf++)
            #pragma unroll
            for (int r = 0; r < 4; r++) c[mf][nf][r] = 0.f;

    #pragma unroll 1
    for (int s = 0; s < NST; s++) {
        const int slot = s & 1;
        CP_WAIT0();                      // stage s landed
        __syncthreads();                 // visible to all; stage s-1 compute done

        if (s + 1 < NST) issue_stage((s + 1) * KS, slot ^ 1);
        CP_COMMIT();                     // always commit (exact accounting)

        const uint32_t Aad = smem_base + A_SL(slot) + alane_off;
        const float* Bsf = (const float*)(smc + B_SL(slot));

        #pragma unroll
        for (int k16 = 0; k16 < 5; k16++) {
            uint32_t a[4][4];
            #pragma unroll
            for (int mf = 0; mf < 4; mf++)
                LDSM_X4(a[mf][0], a[mf][1], a[mf][2], a[mf][3],
                        Aad + mf * 2816 + k16 * 32);
            // B frags: b0 holds k=2tig,2tig+1 (lo,hi); b1 holds k+8,k+9
            uint32_t bf[4][2];
            #pragma unroll
            for (int nf = 0; nf < 4; nf++) {
                const float* bp = Bsf + (k16 * 16 + 2 * tig) * 140 + bcol0 + nf * 8;
                bf[nf][0] = cvt_f16x2(bp[0],       bp[140]);
                bf[nf][1] = cvt_f16x2(bp[8 * 140], bp[9 * 140]);
            }
            #pragma unroll
            for (int mf = 0; mf < 4; mf++)
                #pragma unroll
                for (int nf = 0; nf < 4; nf++)
                    mma_f16(c[mf][nf], a[mf][0], a[mf][1], a[mf][2], a[mf][3],
                            bf[nf][0], bf[nf][1]);
        }
    }
    __syncthreads();   // all MMAs done before h1 overlay overwrites the ring

    // ---- epilogue: relu(D + b1) -> h1[h][i] (stride 136), float2 stores ----
    {
        const float* eB1 = (const float*)(smc + EP_B1);
        float* h1 = (float*)(smc + EP_H1);
        #pragma unroll
        for (int mf = 0; mf < 4; mf++) {
            #pragma unroll
            for (int half = 0; half < 2; half++) {
                const int h = warp_h + mf * 16 + g4 + half * 8;
                const float bv = eB1[h];
                #pragma unroll
                for (int nf = 0; nf < 4; nf++) {
                    const int i = warp_i + nf * 8 + 2 * tig;
                    float2 v;
                    v.x = fmaxf(c[mf][nf][half * 2]     + bv, 0.f);
                    v.y = fmaxf(c[mf][nf][half * 2 + 1] + bv, 0.f);
                    *(float2*)(h1 + h * 136 + i) = v;
                }
            }
        }
        // stage W2t into its post-ring home (disjoint from h1)
        float* eW2 = (float*)(smc + EP_W2);
        for (int idx = tid; idx < H1_ * H2_; idx += 512) eW2[idx] = g_W2t[idx];
    }
    __syncthreads();

    // ---- layer 2: H2[g][i] = relu(W2 @ h1 + b2); 4 gq x 128 i, f32x2 ----
    {
        const int gq = tid >> 7;          // 0..3 -> 4 g each (2 pairs)
        const int il = tid & 127;
        const float* h1 = (const float*)(smc + EP_H1);
        const float* eW2 = (const float*)(smc + EP_W2);
        const float* eB2 = (const float*)(smc + EP_B2);

        unsigned long long a2p[2];
        #pragma unroll
        for (int p = 0; p < 2; p++)
            a2p[p] = *(const unsigned long long*)(eB2 + gq * 4 + p * 2);

        #pragma unroll 8
        for (int h = 0; h < H1_; h++) {
            const uint32_t xu = __float_as_uint(h1[h * 136 + il]);
            unsigned long long xx; PACK2(xx, xu, xu);
            const unsigned long long* wp =
                (const unsigned long long*)(eW2 + h * H2_ + gq * 4);
            FMA2(a2p[0], xx, wp[0], a2p[0]);
            FMA2(a2p[1], xx, wp[1], a2p[1]);
        }
        float* H2s = (float*)(smc + EP_H2);          // [16][132]
        #pragma unroll
        for (int p = 0; p < 2; p++) {
            uint32_t lo, hi;
            UNPACK2(lo, hi, a2p[p]);
            H2s[(gq * 4 + p * 2)     * 132 + il] = fmaxf(__uint_as_float(lo), 0.f);
            H2s[(gq * 4 + p * 2 + 1) * 132 + il] = fmaxf(__uint_as_float(hi), 0.f);
        }
    }
    __syncthreads();

    // ---- layer 3: sec[i] = W3 @ H2 + b3 -> g_fc ----
    if (tid < IT_M) {
        const float* H2s = (const float*)(smc + EP_H2);
        const float* eW3 = (const float*)(smc + EP_W3);
        float sec = *(const float*)(smc + EP_B3);
        #pragma unroll
        for (int g = 0; g < H2_; g++)
            sec += eW3[g] * H2s[g * 132 + tid];
        const int gi = i0 + tid;
        if (gi < IV) g_fc[b * IV + gi] = sec;
    }
}

// ---------------------------------------------------------------------------
// Kernel 2: predictor. Grid 64 blocks x 256 thr; 4 batches per block.
// ---------------------------------------------------------------------------
__global__ __launch_bounds__(256)
void pred_kernel(const float* __restrict__ bp,
                 const float* __restrict__ Wv, const float* __restrict__ bv,
                 float* __restrict__ out)
{
    __shared__ float fcsT[IV * 4 + 8];     // [k][4 batches]
    __shared__ float red[4][PH_];
    const int b0 = blockIdx.x * 4;
    const int tid = threadIdx.x;

    #pragma unroll
    for (int r = 0; r < 4; r++)
        for (int k = tid; k < IV; k += 256)
            fcsT[k * 4 + r] = g_fc[(b0 + r) * IV + k];
    __syncthreads();

    const int ph = tid;
    unsigned long long a01 = 0ull, a23 = 0ull;
    const float* wpt = g_WpT + ph;
    #pragma unroll 4
    for (int k = 0; k < IV; k++) {
        const uint32_t wu = __float_as_uint(wpt[(size_t)k * PH_]);   // coalesced
        unsigned long long ww; PACK2(ww, wu, wu);
        const unsigned long long p01 = *(const unsigned long long*)(fcsT + k * 4);
        const unsigned long long p23 = *(const unsigned long long*)(fcsT + k * 4 + 2);
        FMA2(a01, ww, p01, a01);
        FMA2(a23, ww, p23, a23);
    }
    uint32_t u0, u1, u2, u3;
    UNPACK2(u0, u1, a01);
    UNPACK2(u2, u3, a23);
    const float bpv = bp[ph], wvv = Wv[ph];
    red[0][ph] = fmaxf(__uint_as_float(u0) + bpv, 0.f) * wvv;
    red[1][ph] = fmaxf(__uint_as_float(u1) + bpv, 0.f) * wvv;
    red[2][ph] = fmaxf(__uint_as_float(u2) + bpv, 0.f) * wvv;
    red[3][ph] = fmaxf(__uint_as_float(u3) + bpv, 0.f) * wvv;
    __syncthreads();
    for (int s = 128; s > 0; s >>= 1) {
        if (tid < s) {
            #pragma unroll
            for (int r = 0; r < 4; r++) red[r][tid] += red[r][tid + s];
        }
        __syncthreads();
    }
    if (tid == 0) {
        const float bvv = bv[0];
        #pragma unroll
        for (int r = 0; r < 4; r++) out[b0 + r] = red[r][0] + bvv;
    }
}

// ---------------------------------------------------------------------------
extern "C" void kernel_launch(void* const* d_in, const int* in_sizes, int n_in,
                              void* d_out, int out_size)
{
    const float* state = (const float*)d_in[0];
    const float* W1    = (const float*)d_in[1];
    const float* b1    = (const float*)d_in[2];
    const float* W2    = (const float*)d_in[3];
    const float* b2    = (const float*)d_in[4];
    const float* W3    = (const float*)d_in[5];
    const float* b3    = (const float*)d_in[6];
    const float* Wp    = (const float*)d_in[7];
    const float* bp    = (const float*)d_in[8];
    const float* Wv    = (const float*)d_in[9];
    const float* bv    = (const float*)d_in[10];
    float* out = (float*)d_out;

    cudaFuncSetAttribute(section_kernel,
                         cudaFuncAttributeMaxDynamicSharedMemorySize, SMEM_BYTES);

    prep_all<<<(PH_ * IV + 255) / 256, 256>>>(W1, W2, Wp);

    dim3 grid(NIT, B_);
    section_kernel<<<grid, 512, SMEM_BYTES>>>(state, b1, b2, W3, b3);
    pred_kernel<<<64, 256>>>(bp, Wv, bv, out);
}